// round 10
// baseline (speedup 1.0000x reference)
#include <cuda_runtime.h>
#include <cuda_fp16.h>
#include <math.h>

#define BATCH 16
#define CH    64
#define NPIX  25600          // 160*160
#define HID   256
#define KSEL  20480          // ceil(25600*0.8)
#define TOKB  128            // tokens per block
#define NTHR  256            // 8 warps

#define ST_S  68             // sT fp32 row stride (272B)
#define W1_S  136            // fp16 elements per row (272B), chunk rows=64
#define W2_S  72             // fp16 elements per row (144B), chunk rows=128

// smem byte offsets (main kernel)
#define OFF_T    0            // 128*68*4  = 34816
#define OFF_W    34816        // FOUR chunk buffers, each 35840 (W1 17408 + W2 18432)
#define BUFB     35840
#define OFF_B1   178176       // 256 u32 (h2-packed bias1)
#define OFF_B2   179200       // 2*64*4 = 512
#define OFF_LS   179712       // 512
#define OFF_LB   180224       // 512
#define OFF_FLAG 180736       // 128*4 = 512
#define OFF_MBAR 181248       // 4 mbarriers x 8B
#define SMEM_BYTES 181312

// ---------------- static scratch ----------------
__device__ unsigned      g_thresh[BATCH];
__device__ int           g_ties[BATCH];
__device__ unsigned char g_flags[BATCH * NPIX];
// pre-converted fp16 weights in smem tile layout (chunk = layer*2 + jc)
__device__ __align__(16) unsigned short g_w1[4 * 64 * W1_S];
__device__ __align__(16) unsigned short g_w2[4 * 128 * W2_S];

__device__ __forceinline__ unsigned fkey(float f) {
    unsigned u = __float_as_uint(f);
    return (u & 0x80000000u) ? ~u : (u | 0x80000000u);
}

__device__ __forceinline__ unsigned pack_h2(float2 v) {
    __half2 h = __float22half2_rn(v);
    return *(unsigned*)&h;
}

// gelu on a packed half2 (tanh approximation, all-fp16 math)
__device__ __forceinline__ unsigned gelu_h2(unsigned vu) {
    __half2 v = *(__half2*)&vu;
    const __half2 k0  = __floats2half2_rn(0.7978845608f, 0.7978845608f);
    const __half2 k01 = __floats2half2_rn(0.0356774081f, 0.0356774081f);  // k0*0.044715
    const __half2 hf  = __floats2half2_rn(0.5f, 0.5f);
    __half2 u = __hmul2(v, v);
    __half2 w = __hmul2(u, v);
    __half2 inner = __hfma2(w, k01, __hmul2(v, k0));
    unsigned tin = *(unsigned*)&inner, tout;
    asm("tanh.approx.f16x2 %0, %1;" : "=r"(tout) : "r"(tin));
    __half2 t = *(__half2*)&tout;
    __half2 hv = __hmul2(v, hf);
    __half2 res = __hfma2(hv, t, hv);
    return *(unsigned*)&res;
}

__device__ __forceinline__ void ldsm_x4t(unsigned* r, unsigned addr) {
    asm volatile("ldmatrix.sync.aligned.m8n8.x4.trans.shared.b16 {%0,%1,%2,%3}, [%4];"
                 : "=r"(r[0]), "=r"(r[1]), "=r"(r[2]), "=r"(r[3]) : "r"(addr));
}
__device__ __forceinline__ void mma_f16(float* d, const unsigned* a, unsigned b0, unsigned b1) {
    asm volatile("mma.sync.aligned.m16n8k16.row.col.f32.f16.f16.f32 "
                 "{%0,%1,%2,%3}, {%4,%5,%6,%7}, {%8,%9}, {%0,%1,%2,%3};"
                 : "+f"(d[0]), "+f"(d[1]), "+f"(d[2]), "+f"(d[3])
                 : "r"(a[0]), "r"(a[1]), "r"(a[2]), "r"(a[3]), "r"(b0), "r"(b1));
}
__device__ __forceinline__ void mbar_wait(unsigned mbar, unsigned parity) {
    asm volatile("{\n\t.reg .pred P;\n\tWL_%=:\n\t"
                 "mbarrier.try_wait.parity.acquire.cta.shared::cta.b64 P, [%0], %1, 0x989680;\n\t"
                 "@P bra.uni WD_%=;\n\tbra.uni WL_%=;\n\tWD_%=:\n\t}"
                 :: "r"(mbar), "r"(parity) : "memory");
}
__device__ __forceinline__ void bulk_cp(unsigned dst, const void* src, unsigned bytes, unsigned mbar) {
    asm volatile("cp.async.bulk.shared::cta.global.mbarrier::complete_tx::bytes [%0], [%1], %2, [%3];"
                 :: "r"(dst), "l"(src), "r"(bytes), "r"(mbar) : "memory");
}

// ---------------- kernel 1: fused prep + per-batch radix select + flags ----------------
__global__ void select_flags_kernel(const float* __restrict__ prop,
                                    const float* __restrict__ w1g, const float* __restrict__ w2g) {
    int tid = threadIdx.x;
    if (blockIdx.x >= BATCH) {
        // ---- prep: pre-convert weights to fp16 smem-tile layout ----
        int base = (blockIdx.x - BATCH) * 16384;
        #pragma unroll 4
        for (int q = 0; q < 16; ++q) {
            int idx = base + q * 1024 + tid;
            int layer = idx >> 14;
            int rem = idx & 16383;
            {   // w1: [layer][c][j]
                int c = rem >> 8, j = rem & 255;
                __half h = __float2half_rn(w1g[idx]);
                int off = (layer * 2 + (j >> 7)) * 64 * W1_S + c * W1_S + (j & 127);
                g_w1[off] = *(unsigned short*)&h;
            }
            {   // w2: [layer][j][c]
                int j = rem >> 6, c = rem & 63;
                __half h = __float2half_rn(w2g[idx]);
                int off = (layer * 2 + (j >> 7)) * 128 * W2_S + (j & 127) * W2_S + c;
                g_w2[off] = *(unsigned short*)&h;
            }
        }
        return;
    }
    int b = blockIdx.x;
    const float* p = prop + (size_t)b * NPIX;
    extern __shared__ unsigned dyn[];
    unsigned* skey = dyn;              // 25600 keys
    unsigned* hist = dyn + NPIX;       // 256
    __shared__ unsigned s_prefix;
    __shared__ int s_k;
    __shared__ int s_carry;
    __shared__ unsigned wtot[8];
    __shared__ int warp_sums[32];
    if (tid == 0) { s_prefix = 0u; s_k = KSEL; s_carry = 0; }
    for (int i = tid; i < NPIX; i += 1024) skey[i] = fkey(p[i]);
    __syncthreads();

    for (int pass = 3; pass >= 0; --pass) {
        int shift = pass * 8;
        if (tid < 256) hist[tid] = 0u;
        __syncthreads();
        unsigned prefix = s_prefix;
        unsigned highmask = (pass == 3) ? 0u : (0xFFFFFFFFu << (shift + 8));
        for (int i = tid; i < NPIX; i += 1024) {
            unsigned u = skey[i];
            if ((u & highmask) == prefix)
                atomicAdd(&hist[(u >> shift) & 255u], 1u);
        }
        __syncthreads();
        // ---- parallel suffix-sum digit selection (256 threads) ----
        int k = s_k;
        unsigned v = 0, h0 = 0;
        int l = tid & 31, w8 = tid >> 5;
        if (tid < 256) {
            v = hist[tid];
            h0 = v;
            #pragma unroll
            for (int off = 1; off < 32; off <<= 1) {
                unsigned t = __shfl_down_sync(0xffffffffu, v, off);
                if (l + off < 32) v += t;
            }
            if (l == 0) wtot[w8] = v;
        }
        __syncthreads();
        if (tid < 256) {
            unsigned suf = v;
            for (int q = w8 + 1; q < 8; ++q) suf += wtot[q];
            if ((int)suf >= k && (int)(suf - h0) < k) {
                s_prefix = prefix | ((unsigned)tid << shift);
                s_k = k - (int)(suf - h0);
            }
        }
        __syncthreads();
    }
    unsigned T = s_prefix;
    int ties = s_k;
    int lane = tid & 31, w = tid >> 5;
    for (int base = 0; base < NPIX; base += 1024) {
        int i = base + tid;
        unsigned u = skey[i];
        int gt = (u > T), eq = (u == T);
        unsigned ball = __ballot_sync(0xffffffffu, eq);
        int pre = __popc(ball & ((1u << lane) - 1u));
        if (lane == 0) warp_sums[w] = __popc(ball);
        __syncthreads();
        int woff = 0;
        for (int xw = 0; xw < w; ++xw) woff += warp_sums[xw];
        int rank = s_carry + woff + pre;
        g_flags[(size_t)b * NPIX + i] = (unsigned char)(gt || (eq && rank < ties));
        __syncthreads();
        if (tid == 0) {
            int tot = 0;
            for (int xw = 0; xw < 32; ++xw) tot += warp_sums[xw];
            s_carry += tot;
        }
        __syncthreads();
    }
}

// ---------------- kernel 2: fused LN + MLP, fp16, barrier-free mainloop ----------
__global__ void __launch_bounds__(NTHR, 1)
main_kernel(const float* __restrict__ x,
            const float* __restrict__ lnscale, const float* __restrict__ lnbias,
            const float* __restrict__ b1g, const float* __restrict__ b2g,
            float* __restrict__ out) {
    extern __shared__ char sm[];
    float* sT  = (float*)(sm + OFF_T);
    unsigned* sB1h = (unsigned*)(sm + OFF_B1);
    float* sB2 = (float*)(sm + OFF_B2);
    float* sLS = (float*)(sm + OFF_LS);
    float* sLB = (float*)(sm + OFF_LB);
    int*   sFlag = (int*)(sm + OFF_FLAG);
    unsigned smem_base = (unsigned)__cvta_generic_to_shared(sm);

    int tid = threadIdx.x;
    int lane = tid & 31, w = tid >> 5;
    int tb = w * 16;
    int b = blockIdx.y, n0 = blockIdx.x * TOKB;

    int r = lane >> 2;           // fragment row within 8
    int c2 = (lane & 3) * 2;     // fragment col pair
    int r15 = lane & 15;
    int colsel = ((lane >> 4) & 1) * 8;
    int row0 = tb + r, row1 = row0 + 8;

    // ---- init mbarriers (before the block sync) ----
    if (tid == 0) {
        #pragma unroll
        for (int ch = 0; ch < 4; ++ch)
            asm volatile("mbarrier.init.shared.b64 [%0], %1;"
                         :: "r"(smem_base + OFF_MBAR + ch * 8), "r"(1u) : "memory");
    }

    // ---- load x tile: sT[t][c], params, flags ----
    const float* xb = x + (size_t)b * CH * NPIX + n0;
    for (int i = tid; i < TOKB * CH; i += NTHR) {
        int t = i & (TOKB - 1);
        int c = i >> 7;
        sT[t * ST_S + c] = xb[(size_t)c * NPIX + t];
    }
    if (tid < HID) sB1h[tid] = pack_h2(make_float2(b1g[2 * tid], b1g[2 * tid + 1]));
    if (tid < 2 * CH) {
        sB2[tid] = b2g[tid];
        sLS[tid] = lnscale[tid];
        sLB[tid] = lnbias[tid];
    }
    if (tid < TOKB) sFlag[tid] = g_flags[(size_t)b * NPIX + n0 + tid];
    __syncthreads();   // sT + params + mbarrier init visible

    // ---- single thread stages all 4 weight chunks (bulk async, mbarrier-tracked) ----
    if (tid == 0) {
        #pragma unroll
        for (int ch = 0; ch < 4; ++ch) {
            unsigned mbar = smem_base + OFF_MBAR + ch * 8;
            asm volatile("mbarrier.arrive.expect_tx.shared.b64 _, [%0], %1;"
                         :: "r"(mbar), "r"((unsigned)BUFB) : "memory");
            unsigned dst = smem_base + OFF_W + ch * BUFB;
            bulk_cp(dst,         g_w1 + ch * 64 * W1_S,  64 * W1_S * 2,  mbar);
            bulk_cp(dst + 17408, g_w2 + ch * 128 * W2_S, 128 * W2_S * 2, mbar);
        }
    }

    for (int layer = 0; layer < 2; ++layer) {
        // ---- LN stats (warp-local): 2 lanes per token ----
        float mu, rs;
        {
            int t = tb + (lane >> 1), half = lane & 1;
            const float* rowp = sT + t * ST_S + half * 32;
            float s = 0.f, s2 = 0.f;
            #pragma unroll
            for (int k = 0; k < 32; k += 4) {
                float4 v = *(const float4*)(rowp + k);
                s  += v.x + v.y + v.z + v.w;
                s2 += v.x * v.x + v.y * v.y + v.z * v.z + v.w * v.w;
            }
            s  += __shfl_xor_sync(0xffffffffu, s, 1);
            s2 += __shfl_xor_sync(0xffffffffu, s2, 1);
            mu = s * (1.f / 64.f);
            float var = s2 * (1.f / 64.f) - mu * mu;
            rs = rsqrtf(var + 1e-5f);
        }
        float mu0 = __shfl_sync(0xffffffffu, mu, r << 1);
        float rs0 = __shfl_sync(0xffffffffu, rs, r << 1);
        float mu1 = __shfl_sync(0xffffffffu, mu, (r << 1) + 16);
        float rs1 = __shfl_sync(0xffffffffu, rs, (r << 1) + 16);

        // ---- build GEMM1 A-fragments (Xn) in registers, fp16 ----
        unsigned aX[16];
        #pragma unroll
        for (int kt = 0; kt < 4; ++kt) {
            int cA = kt * 16 + c2;
            float2 lsA = *(const float2*)(sLS + layer * 64 + cA);
            float2 lbA = *(const float2*)(sLB + layer * 64 + cA);
            float2 lsB = *(const float2*)(sLS + layer * 64 + cA + 8);
            float2 lbB = *(const float2*)(sLB + layer * 64 + cA + 8);
            float2 v;
            v = *(const float2*)(sT + row0 * ST_S + cA);
            v.x = (v.x - mu0) * rs0 * lsA.x + lbA.x;
            v.y = (v.y - mu0) * rs0 * lsA.y + lbA.y;
            aX[kt * 4 + 0] = pack_h2(v);
            v = *(const float2*)(sT + row1 * ST_S + cA);
            v.x = (v.x - mu1) * rs1 * lsA.x + lbA.x;
            v.y = (v.y - mu1) * rs1 * lsA.y + lbA.y;
            aX[kt * 4 + 1] = pack_h2(v);
            v = *(const float2*)(sT + row0 * ST_S + cA + 8);
            v.x = (v.x - mu0) * rs0 * lsB.x + lbB.x;
            v.y = (v.y - mu0) * rs0 * lsB.y + lbB.y;
            aX[kt * 4 + 2] = pack_h2(v);
            v = *(const float2*)(sT + row1 * ST_S + cA + 8);
            v.x = (v.x - mu1) * rs1 * lsB.x + lbB.x;
            v.y = (v.y - mu1) * rs1 * lsB.y + lbB.y;
            aX[kt * 4 + 3] = pack_h2(v);
        }

        float d2[32];
        #pragma unroll
        for (int i = 0; i < 32; ++i) d2[i] = 0.f;

        for (int jc = 0; jc < 2; ++jc) {
            int ch = layer * 2 + jc;
            unsigned wbase = smem_base + OFF_W + ch * BUFB;

            // ---- warp-local wait for this chunk's weights (no block barrier) ----
            mbar_wait(smem_base + OFF_MBAR + ch * 8, 0);

            // ---- pipeline prologue: W1 B-frags for jg=0 ----
            unsigned bh1[16], bh2[16];
            #pragma unroll
            for (int kt = 0; kt < 4; ++kt)
                ldsm_x4t(bh1 + kt * 4, wbase + (unsigned)((kt * 16 + r15) * W1_S + colsel) * 2);

            #pragma unroll
            for (int jg = 0; jg < 8; ++jg) {
                // ---- GEMM1 MMAs with resident bh1; interleave W2 ldsm for this jg ----
                float d1[8];
                #pragma unroll
                for (int i = 0; i < 8; ++i) d1[i] = 0.f;
                #pragma unroll
                for (int kt = 0; kt < 4; ++kt) {
                    ldsm_x4t(bh2 + kt * 4,
                             wbase + 17408 + (unsigned)((jg * 16 + r15) * W2_S + kt * 16 + colsel) * 2);
                    mma_f16(d1,     aX + kt * 4, bh1[kt * 4],     bh1[kt * 4 + 1]);
                    mma_f16(d1 + 4, aX + kt * 4, bh1[kt * 4 + 2], bh1[kt * 4 + 3]);
                }
                // ---- epilogue in h2: pack + bias + gelu -> GEMM2 A frags ----
                unsigned a2[4];
                {
                    int j0 = jc * 128 + jg * 16;
                    int pb = (layer * HID + j0) >> 1;
                    unsigned b0 = sB1h[pb + (c2 >> 1)];
                    unsigned b8 = sB1h[pb + 4 + (c2 >> 1)];
                    __half2 b0h = *(__half2*)&b0, b8h = *(__half2*)&b8;
                    __half2 t; unsigned tu;
                    #define GEPI(dst, dd, bb) \
                        tu = pack_h2(make_float2((dd)[0], (dd)[1])); \
                        t = __hadd2(*(__half2*)&tu, bb); \
                        dst = gelu_h2(*(unsigned*)&t);
                    GEPI(a2[0], d1 + 0, b0h); GEPI(a2[1], d1 + 2, b0h);
                    GEPI(a2[2], d1 + 4, b8h); GEPI(a2[3], d1 + 6, b8h);
                    #undef GEPI
                }
                // ---- GEMM2 MMAs with resident bh2; interleave W1 ldsm for jg+1 ----
                int jn = (jg + 1) & 7;
                #pragma unroll
                for (int np = 0; np < 4; ++np) {
                    ldsm_x4t(bh1 + np * 4,
                             wbase + (unsigned)((np * 16 + r15) * W1_S + jn * 16 + colsel) * 2);
                    mma_f16(d2 + np * 8,     a2, bh2[np * 4],     bh2[np * 4 + 1]);
                    mma_f16(d2 + np * 8 + 4, a2, bh2[np * 4 + 2], bh2[np * 4 + 3]);
                }
            }
        }

        // ---- gated residual add into sT (warp-local rows) ----
        {
            int f0 = sFlag[row0], f1 = sFlag[row1];
            #pragma unroll
            for (int nt = 0; nt < 8; ++nt) {
                int c0 = nt * 8 + c2;
                float2 bv = *(const float2*)(sB2 + layer * 64 + c0);
                if (f0) {
                    sT[row0 * ST_S + c0]     += d2[nt * 4 + 0] + bv.x;
                    sT[row0 * ST_S + c0 + 1] += d2[nt * 4 + 1] + bv.y;
                }
                if (f1) {
                    sT[row1 * ST_S + c0]     += d2[nt * 4 + 2] + bv.x;
                    sT[row1 * ST_S + c0 + 1] += d2[nt * 4 + 3] + bv.y;
                }
            }
        }
        __syncwarp();
    }

    // ---- store tile ----
    __syncthreads();
    float* ob = out + (size_t)b * CH * NPIX + n0;
    for (int i = tid; i < TOKB * CH; i += NTHR) {
        int t = i & (TOKB - 1);
        int c = i >> 7;
        ob[(size_t)c * NPIX + t] = sT[t * ST_S + c];
    }
}

// ---------------- launch ----------------
extern "C" void kernel_launch(void* const* d_in, const int* in_sizes, int n_in,
                              void* d_out, int out_size) {
    const float* x    = (const float*)d_in[0];
    const float* prop = (const float*)d_in[1];
    const float* lns  = (const float*)d_in[2];
    const float* lnb  = (const float*)d_in[3];
    const float* w1   = (const float*)d_in[4];
    const float* b1   = (const float*)d_in[5];
    const float* w2   = (const float*)d_in[6];
    const float* b2   = (const float*)d_in[7];
    float* out = (float*)d_out;

    cudaFuncSetAttribute(main_kernel, cudaFuncAttributeMaxDynamicSharedMemorySize, SMEM_BYTES);
    int sel_smem = (NPIX + 260) * 4;
    cudaFuncSetAttribute(select_flags_kernel, cudaFuncAttributeMaxDynamicSharedMemorySize, sel_smem);

    select_flags_kernel<<<BATCH + 2, 1024, sel_smem>>>(prop, w1, w2);
    dim3 grid(NPIX / TOKB, BATCH);
    main_kernel<<<grid, NTHR, SMEM_BYTES>>>(x, lns, lnb, b1, b2, out);
}

// round 11
// speedup vs baseline: 1.9525x; 1.9525x over previous
#include <cuda_runtime.h>
#include <cuda_fp16.h>
#include <math.h>

#define BATCH 16
#define CH    64
#define NPIX  25600          // 160*160
#define HID   256
#define KSEL  20480          // ceil(25600*0.8)
#define TOKB  128            // tokens per block
#define NTHR  256            // 8 warps

#define ST_S  68             // sT fp32 row stride (272B)
#define W1_S  136            // fp16 elements per row (272B), chunk rows=64
#define W2_S  72             // fp16 elements per row (144B), chunk rows=128

// smem byte offsets (main kernel) -- SINGLE weight buffer for occupancy 3
#define OFF_T    0            // 128*68*4  = 34816
#define OFF_W    34816        // one chunk buffer 35840 (W1 17408 + W2 18432)
#define OFF_B1   70656        // 256 u32 (h2-packed bias1)
#define OFF_B2   71680        // 2*64*4 = 512
#define OFF_LS   72192        // 512
#define OFF_LB   72704        // 512
#define OFF_FLAG 73216        // 128*4 = 512
#define SMEM_BYTES 73728      // x3 CTAs = 221184 <= 227KB

// ---------------- static scratch ----------------
__device__ unsigned      g_thresh[BATCH];
__device__ int           g_ties[BATCH];
__device__ unsigned char g_flags[BATCH * NPIX];
// pre-converted fp16 weights in smem tile layout (chunk = layer*2 + jc)
__device__ __align__(16) unsigned short g_w1[4 * 64 * W1_S];
__device__ __align__(16) unsigned short g_w2[4 * 128 * W2_S];

__device__ __forceinline__ unsigned fkey(float f) {
    unsigned u = __float_as_uint(f);
    return (u & 0x80000000u) ? ~u : (u | 0x80000000u);
}

__device__ __forceinline__ unsigned pack_h2(float2 v) {
    __half2 h = __float22half2_rn(v);
    return *(unsigned*)&h;
}

// gelu on a packed half2 (tanh approximation, all-fp16 math)
__device__ __forceinline__ unsigned gelu_h2(unsigned vu) {
    __half2 v = *(__half2*)&vu;
    const __half2 k0  = __floats2half2_rn(0.7978845608f, 0.7978845608f);
    const __half2 k01 = __floats2half2_rn(0.0356774081f, 0.0356774081f);  // k0*0.044715
    const __half2 hf  = __floats2half2_rn(0.5f, 0.5f);
    __half2 u = __hmul2(v, v);
    __half2 w = __hmul2(u, v);
    __half2 inner = __hfma2(w, k01, __hmul2(v, k0));
    unsigned tin = *(unsigned*)&inner, tout;
    asm("tanh.approx.f16x2 %0, %1;" : "=r"(tout) : "r"(tin));
    __half2 t = *(__half2*)&tout;
    __half2 hv = __hmul2(v, hf);
    __half2 res = __hfma2(hv, t, hv);
    return *(unsigned*)&res;
}

__device__ __forceinline__ void ldsm_x4t(unsigned* r, unsigned addr) {
    asm volatile("ldmatrix.sync.aligned.m8n8.x4.trans.shared.b16 {%0,%1,%2,%3}, [%4];"
                 : "=r"(r[0]), "=r"(r[1]), "=r"(r[2]), "=r"(r[3]) : "r"(addr));
}
__device__ __forceinline__ void mma_f16(float* d, const unsigned* a, unsigned b0, unsigned b1) {
    asm volatile("mma.sync.aligned.m16n8k16.row.col.f32.f16.f16.f32 "
                 "{%0,%1,%2,%3}, {%4,%5,%6,%7}, {%8,%9}, {%0,%1,%2,%3};"
                 : "+f"(d[0]), "+f"(d[1]), "+f"(d[2]), "+f"(d[3])
                 : "r"(a[0]), "r"(a[1]), "r"(a[2]), "r"(a[3]), "r"(b0), "r"(b1));
}
__device__ __forceinline__ void cp16(unsigned dst, const void* src) {
    asm volatile("cp.async.cg.shared.global [%0], [%1], 16;" :: "r"(dst), "l"(src));
}

// ---------------- kernel 1: fused prep + per-batch radix select + flags ----------------
__global__ void select_flags_kernel(const float* __restrict__ prop,
                                    const float* __restrict__ w1g, const float* __restrict__ w2g) {
    int tid = threadIdx.x;
    if (blockIdx.x >= BATCH) {
        // ---- prep: pre-convert weights to fp16 smem-tile layout ----
        int base = (blockIdx.x - BATCH) * 16384;
        #pragma unroll 4
        for (int q = 0; q < 16; ++q) {
            int idx = base + q * 1024 + tid;
            int layer = idx >> 14;
            int rem = idx & 16383;
            {   // w1: [layer][c][j]
                int c = rem >> 8, j = rem & 255;
                __half h = __float2half_rn(w1g[idx]);
                int off = (layer * 2 + (j >> 7)) * 64 * W1_S + c * W1_S + (j & 127);
                g_w1[off] = *(unsigned short*)&h;
            }
            {   // w2: [layer][j][c]
                int j = rem >> 6, c = rem & 63;
                __half h = __float2half_rn(w2g[idx]);
                int off = (layer * 2 + (j >> 7)) * 128 * W2_S + (j & 127) * W2_S + c;
                g_w2[off] = *(unsigned short*)&h;
            }
        }
        return;
    }
    int b = blockIdx.x;
    const float* p = prop + (size_t)b * NPIX;
    extern __shared__ unsigned dyn[];
    unsigned* skey = dyn;              // 25600 keys
    unsigned* hist = dyn + NPIX;       // 256
    __shared__ unsigned s_prefix;
    __shared__ int s_k;
    __shared__ int s_carry;
    __shared__ unsigned wtot[8];
    __shared__ int warp_sums[32];
    if (tid == 0) { s_prefix = 0u; s_k = KSEL; s_carry = 0; }
    for (int i = tid; i < NPIX; i += 1024) skey[i] = fkey(p[i]);
    __syncthreads();

    for (int pass = 3; pass >= 0; --pass) {
        int shift = pass * 8;
        if (tid < 256) hist[tid] = 0u;
        __syncthreads();
        unsigned prefix = s_prefix;
        unsigned highmask = (pass == 3) ? 0u : (0xFFFFFFFFu << (shift + 8));
        for (int i = tid; i < NPIX; i += 1024) {
            unsigned u = skey[i];
            if ((u & highmask) == prefix)
                atomicAdd(&hist[(u >> shift) & 255u], 1u);
        }
        __syncthreads();
        // ---- parallel suffix-sum digit selection (256 threads) ----
        int k = s_k;
        unsigned v = 0, h0 = 0;
        int l = tid & 31, w8 = tid >> 5;
        if (tid < 256) {
            v = hist[tid];
            h0 = v;
            #pragma unroll
            for (int off = 1; off < 32; off <<= 1) {
                unsigned t = __shfl_down_sync(0xffffffffu, v, off);
                if (l + off < 32) v += t;
            }
            if (l == 0) wtot[w8] = v;
        }
        __syncthreads();
        if (tid < 256) {
            unsigned suf = v;
            for (int q = w8 + 1; q < 8; ++q) suf += wtot[q];
            if ((int)suf >= k && (int)(suf - h0) < k) {
                s_prefix = prefix | ((unsigned)tid << shift);
                s_k = k - (int)(suf - h0);
            }
        }
        __syncthreads();
    }
    unsigned T = s_prefix;
    int ties = s_k;
    int lane = tid & 31, w = tid >> 5;
    for (int base = 0; base < NPIX; base += 1024) {
        int i = base + tid;
        unsigned u = skey[i];
        int gt = (u > T), eq = (u == T);
        unsigned ball = __ballot_sync(0xffffffffu, eq);
        int pre = __popc(ball & ((1u << lane) - 1u));
        if (lane == 0) warp_sums[w] = __popc(ball);
        __syncthreads();
        int woff = 0;
        for (int xw = 0; xw < w; ++xw) woff += warp_sums[xw];
        int rank = s_carry + woff + pre;
        g_flags[(size_t)b * NPIX + i] = (unsigned char)(gt || (eq && rank < ties));
        __syncthreads();
        if (tid == 0) {
            int tot = 0;
            for (int xw = 0; xw < 32; ++xw) tot += warp_sums[xw];
            s_carry += tot;
        }
        __syncthreads();
    }
}

// ---------------- kernel 2: fused LN + MLP, fp16, single-buffer weights, occ 3 ----------
__global__ void __launch_bounds__(NTHR, 3)
main_kernel(const float* __restrict__ x,
            const float* __restrict__ lnscale, const float* __restrict__ lnbias,
            const float* __restrict__ b1g, const float* __restrict__ b2g,
            float* __restrict__ out) {
    extern __shared__ char sm[];
    float* sT  = (float*)(sm + OFF_T);
    unsigned* sB1h = (unsigned*)(sm + OFF_B1);
    float* sB2 = (float*)(sm + OFF_B2);
    float* sLS = (float*)(sm + OFF_LS);
    float* sLB = (float*)(sm + OFF_LB);
    int*   sFlag = (int*)(sm + OFF_FLAG);
    unsigned smem_base = (unsigned)__cvta_generic_to_shared(sm);

    int tid = threadIdx.x;
    int lane = tid & 31, w = tid >> 5;
    int tb = w * 16;
    int b = blockIdx.y, n0 = blockIdx.x * TOKB;

    int r = lane >> 2;           // fragment row within 8
    int c2 = (lane & 3) * 2;     // fragment col pair
    int r15 = lane & 15;
    int colsel = ((lane >> 4) & 1) * 8;
    int row0 = tb + r, row1 = row0 + 8;

    // ---- stage chunk 0 weights (async, overlaps x-tile gmem loads) ----
    {
        const char* s1 = (const char*)g_w1;
        const char* s2 = (const char*)g_w2;
        unsigned dst = smem_base + OFF_W;
        for (int i = tid * 16; i < 64 * W1_S * 2; i += NTHR * 16) cp16(dst + i, s1 + i);
        for (int i = tid * 16; i < 128 * W2_S * 2; i += NTHR * 16) cp16(dst + 17408 + i, s2 + i);
        asm volatile("cp.async.commit_group;");
    }

    // ---- load x tile: sT[t][c], params, flags ----
    const float* xb = x + (size_t)b * CH * NPIX + n0;
    for (int i = tid; i < TOKB * CH; i += NTHR) {
        int t = i & (TOKB - 1);
        int c = i >> 7;
        sT[t * ST_S + c] = xb[(size_t)c * NPIX + t];
    }
    if (tid < HID) sB1h[tid] = pack_h2(make_float2(b1g[2 * tid], b1g[2 * tid + 1]));
    if (tid < 2 * CH) {
        sB2[tid] = b2g[tid];
        sLS[tid] = lnscale[tid];
        sLB[tid] = lnbias[tid];
    }
    if (tid < TOKB) sFlag[tid] = g_flags[(size_t)b * NPIX + n0 + tid];
    __syncthreads();

    for (int layer = 0; layer < 2; ++layer) {
        // ---- LN stats (warp-local): 2 lanes per token ----
        float mu, rs;
        {
            int t = tb + (lane >> 1), half = lane & 1;
            const float* rowp = sT + t * ST_S + half * 32;
            float s = 0.f, s2 = 0.f;
            #pragma unroll
            for (int k = 0; k < 32; k += 4) {
                float4 v = *(const float4*)(rowp + k);
                s  += v.x + v.y + v.z + v.w;
                s2 += v.x * v.x + v.y * v.y + v.z * v.z + v.w * v.w;
            }
            s  += __shfl_xor_sync(0xffffffffu, s, 1);
            s2 += __shfl_xor_sync(0xffffffffu, s2, 1);
            mu = s * (1.f / 64.f);
            float var = s2 * (1.f / 64.f) - mu * mu;
            rs = rsqrtf(var + 1e-5f);
        }
        float mu0 = __shfl_sync(0xffffffffu, mu, r << 1);
        float rs0 = __shfl_sync(0xffffffffu, rs, r << 1);
        float mu1 = __shfl_sync(0xffffffffu, mu, (r << 1) + 16);
        float rs1 = __shfl_sync(0xffffffffu, rs, (r << 1) + 16);

        // ---- build GEMM1 A-fragments (Xn) in registers, fp16 ----
        unsigned aX[16];
        #pragma unroll
        for (int kt = 0; kt < 4; ++kt) {
            int cA = kt * 16 + c2;
            float2 lsA = *(const float2*)(sLS + layer * 64 + cA);
            float2 lbA = *(const float2*)(sLB + layer * 64 + cA);
            float2 lsB = *(const float2*)(sLS + layer * 64 + cA + 8);
            float2 lbB = *(const float2*)(sLB + layer * 64 + cA + 8);
            float2 v;
            v = *(const float2*)(sT + row0 * ST_S + cA);
            v.x = (v.x - mu0) * rs0 * lsA.x + lbA.x;
            v.y = (v.y - mu0) * rs0 * lsA.y + lbA.y;
            aX[kt * 4 + 0] = pack_h2(v);
            v = *(const float2*)(sT + row1 * ST_S + cA);
            v.x = (v.x - mu1) * rs1 * lsA.x + lbA.x;
            v.y = (v.y - mu1) * rs1 * lsA.y + lbA.y;
            aX[kt * 4 + 1] = pack_h2(v);
            v = *(const float2*)(sT + row0 * ST_S + cA + 8);
            v.x = (v.x - mu0) * rs0 * lsB.x + lbB.x;
            v.y = (v.y - mu0) * rs0 * lsB.y + lbB.y;
            aX[kt * 4 + 2] = pack_h2(v);
            v = *(const float2*)(sT + row1 * ST_S + cA + 8);
            v.x = (v.x - mu1) * rs1 * lsB.x + lbB.x;
            v.y = (v.y - mu1) * rs1 * lsB.y + lbB.y;
            aX[kt * 4 + 3] = pack_h2(v);
        }

        float d2[32];
        #pragma unroll
        for (int i = 0; i < 32; ++i) d2[i] = 0.f;

        for (int jc = 0; jc < 2; ++jc) {
            int ch = layer * 2 + jc;
            unsigned wbase = smem_base + OFF_W;

            // ---- wait for this chunk's weights ----
            asm volatile("cp.async.wait_group 0;");
            __syncthreads();

            for (int jg = 0; jg < 8; ++jg) {
                // ---- GEMM1: d1[16 tok x 16 j], K=64, single-pass fp16 ----
                float d1[8];
                #pragma unroll
                for (int i = 0; i < 8; ++i) d1[i] = 0.f;
                #pragma unroll
                for (int kt = 0; kt < 4; ++kt) {
                    unsigned bh[4];
                    unsigned boff = (unsigned)((kt * 16 + r15) * W1_S + jg * 16 + colsel) * 2;
                    ldsm_x4t(bh, wbase + boff);
                    mma_f16(d1,     aX + kt * 4, bh[0], bh[1]);
                    mma_f16(d1 + 4, aX + kt * 4, bh[2], bh[3]);
                }
                // ---- epilogue in h2: pack + bias + gelu -> GEMM2 A frags ----
                unsigned a2[4];
                {
                    int j0 = jc * 128 + jg * 16;
                    int pb = (layer * HID + j0) >> 1;
                    unsigned b0 = sB1h[pb + (c2 >> 1)];
                    unsigned b8 = sB1h[pb + 4 + (c2 >> 1)];
                    __half2 b0h = *(__half2*)&b0, b8h = *(__half2*)&b8;
                    __half2 t; unsigned tu;
                    #define GEPI(dst, dd, bb) \
                        tu = pack_h2(make_float2((dd)[0], (dd)[1])); \
                        t = __hadd2(*(__half2*)&tu, bb); \
                        dst = gelu_h2(*(unsigned*)&t);
                    GEPI(a2[0], d1 + 0, b0h); GEPI(a2[1], d1 + 2, b0h);
                    GEPI(a2[2], d1 + 4, b8h); GEPI(a2[3], d1 + 6, b8h);
                    #undef GEPI
                }
                // ---- GEMM2 partial: k-tile = this jg, N=64, fp16 ----
                #pragma unroll
                for (int np = 0; np < 4; ++np) {
                    unsigned bh[4];
                    unsigned boff = (unsigned)((jg * 16 + r15) * W2_S + np * 16 + colsel) * 2;
                    ldsm_x4t(bh, wbase + 17408 + boff);
                    mma_f16(d2 + np * 8,     a2, bh[0], bh[1]);
                    mma_f16(d2 + np * 8 + 4, a2, bh[2], bh[3]);
                }
            }
            __syncthreads();   // all warps done with buffer

            // ---- stage next chunk (overlaps residual/LN when crossing layers) ----
            if (ch < 3) {
                int nc = ch + 1;
                const char* s1 = (const char*)(g_w1 + nc * 64 * W1_S);
                const char* s2 = (const char*)(g_w2 + nc * 128 * W2_S);
                unsigned dst = smem_base + OFF_W;
                for (int i = tid * 16; i < 64 * W1_S * 2; i += NTHR * 16) cp16(dst + i, s1 + i);
                for (int i = tid * 16; i < 128 * W2_S * 2; i += NTHR * 16) cp16(dst + 17408 + i, s2 + i);
                asm volatile("cp.async.commit_group;");
            }
        }

        // ---- gated residual add into sT (warp-local rows) ----
        {
            int f0 = sFlag[row0], f1 = sFlag[row1];
            #pragma unroll
            for (int nt = 0; nt < 8; ++nt) {
                int c0 = nt * 8 + c2;
                float2 bv = *(const float2*)(sB2 + layer * 64 + c0);
                if (f0) {
                    sT[row0 * ST_S + c0]     += d2[nt * 4 + 0] + bv.x;
                    sT[row0 * ST_S + c0 + 1] += d2[nt * 4 + 1] + bv.y;
                }
                if (f1) {
                    sT[row1 * ST_S + c0]     += d2[nt * 4 + 2] + bv.x;
                    sT[row1 * ST_S + c0 + 1] += d2[nt * 4 + 3] + bv.y;
                }
            }
        }
        __syncwarp();
    }

    // ---- store tile ----
    __syncthreads();
    float* ob = out + (size_t)b * CH * NPIX + n0;
    for (int i = tid; i < TOKB * CH; i += NTHR) {
        int t = i & (TOKB - 1);
        int c = i >> 7;
        ob[(size_t)c * NPIX + t] = sT[t * ST_S + c];
    }
}

// ---------------- launch ----------------
extern "C" void kernel_launch(void* const* d_in, const int* in_sizes, int n_in,
                              void* d_out, int out_size) {
    const float* x    = (const float*)d_in[0];
    const float* prop = (const float*)d_in[1];
    const float* lns  = (const float*)d_in[2];
    const float* lnb  = (const float*)d_in[3];
    const float* w1   = (const float*)d_in[4];
    const float* b1   = (const float*)d_in[5];
    const float* w2   = (const float*)d_in[6];
    const float* b2   = (const float*)d_in[7];
    float* out = (float*)d_out;

    cudaFuncSetAttribute(main_kernel, cudaFuncAttributeMaxDynamicSharedMemorySize, SMEM_BYTES);
    int sel_smem = (NPIX + 260) * 4;
    cudaFuncSetAttribute(select_flags_kernel, cudaFuncAttributeMaxDynamicSharedMemorySize, sel_smem);

    select_flags_kernel<<<BATCH + 2, 1024, sel_smem>>>(prop, w1, w2);
    dim3 grid(NPIX / TOKB, BATCH);
    main_kernel<<<grid, NTHR, SMEM_BYTES>>>(x, lns, lnb, b1, b2, out);
}

// round 12
// speedup vs baseline: 1.9555x; 1.0016x over previous
#include <cuda_runtime.h>
#include <cuda_fp16.h>
#include <math.h>

#define BATCH 16
#define CH    64
#define NPIX  25600          // 160*160
#define HID   256
#define KSEL  20480          // ceil(25600*0.8)
#define TOKB  128            // tokens per block
#define NTHR  128            // 4 warps x 32 tokens each

#define ST_S  68             // sT fp32 row stride (272B)
#define W1_S  136            // fp16 elements per row (272B), chunk rows=64
#define W2_S  72             // fp16 elements per row (144B), chunk rows=128

// smem byte offsets (main kernel) -- SINGLE weight buffer, occupancy 3
#define OFF_T    0            // 128*68*4  = 34816
#define OFF_W    34816        // one chunk buffer 35840 (W1 17408 + W2 18432)
#define OFF_B1   70656        // 256 u32 (h2-packed bias1)
#define OFF_B2   71680        // 2*64*4 = 512
#define OFF_LS   72192        // 512
#define OFF_LB   72704        // 512
#define OFF_FLAG 73216        // 128*4 = 512
#define SMEM_BYTES 73728      // x3 CTAs = 221184 <= 227KB

// ---------------- static scratch ----------------
__device__ unsigned      g_thresh[BATCH];
__device__ int           g_ties[BATCH];
__device__ unsigned char g_flags[BATCH * NPIX];
// pre-converted fp16 weights in smem tile layout (chunk = layer*2 + jc)
__device__ __align__(16) unsigned short g_w1[4 * 64 * W1_S];
__device__ __align__(16) unsigned short g_w2[4 * 128 * W2_S];

__device__ __forceinline__ unsigned fkey(float f) {
    unsigned u = __float_as_uint(f);
    return (u & 0x80000000u) ? ~u : (u | 0x80000000u);
}

__device__ __forceinline__ unsigned pack_h2(float2 v) {
    __half2 h = __float22half2_rn(v);
    return *(unsigned*)&h;
}

// gelu on a packed half2 (tanh approximation, all-fp16 math)
__device__ __forceinline__ unsigned gelu_h2(unsigned vu) {
    __half2 v = *(__half2*)&vu;
    const __half2 k0  = __floats2half2_rn(0.7978845608f, 0.7978845608f);
    const __half2 k01 = __floats2half2_rn(0.0356774081f, 0.0356774081f);  // k0*0.044715
    const __half2 hf  = __floats2half2_rn(0.5f, 0.5f);
    __half2 u = __hmul2(v, v);
    __half2 w = __hmul2(u, v);
    __half2 inner = __hfma2(w, k01, __hmul2(v, k0));
    unsigned tin = *(unsigned*)&inner, tout;
    asm("tanh.approx.f16x2 %0, %1;" : "=r"(tout) : "r"(tin));
    __half2 t = *(__half2*)&tout;
    __half2 hv = __hmul2(v, hf);
    __half2 res = __hfma2(hv, t, hv);
    return *(unsigned*)&res;
}

__device__ __forceinline__ void ldsm_x4t(unsigned* r, unsigned addr) {
    asm volatile("ldmatrix.sync.aligned.m8n8.x4.trans.shared.b16 {%0,%1,%2,%3}, [%4];"
                 : "=r"(r[0]), "=r"(r[1]), "=r"(r[2]), "=r"(r[3]) : "r"(addr));
}
__device__ __forceinline__ void mma_f16(float* d, const unsigned* a, unsigned b0, unsigned b1) {
    asm volatile("mma.sync.aligned.m16n8k16.row.col.f32.f16.f16.f32 "
                 "{%0,%1,%2,%3}, {%4,%5,%6,%7}, {%8,%9}, {%0,%1,%2,%3};"
                 : "+f"(d[0]), "+f"(d[1]), "+f"(d[2]), "+f"(d[3])
                 : "r"(a[0]), "r"(a[1]), "r"(a[2]), "r"(a[3]), "r"(b0), "r"(b1));
}
__device__ __forceinline__ void cp16(unsigned dst, const void* src) {
    asm volatile("cp.async.cg.shared.global [%0], [%1], 16;" :: "r"(dst), "l"(src));
}

// ---------------- kernel 1: fused prep + per-batch radix select + flags ----------------
__global__ void select_flags_kernel(const float* __restrict__ prop,
                                    const float* __restrict__ w1g, const float* __restrict__ w2g) {
    int tid = threadIdx.x;
    if (blockIdx.x >= BATCH) {
        // ---- prep: pre-convert weights to fp16 smem-tile layout ----
        int base = (blockIdx.x - BATCH) * 16384;
        #pragma unroll 4
        for (int q = 0; q < 16; ++q) {
            int idx = base + q * 1024 + tid;
            int layer = idx >> 14;
            int rem = idx & 16383;
            {   // w1: [layer][c][j]
                int c = rem >> 8, j = rem & 255;
                __half h = __float2half_rn(w1g[idx]);
                int off = (layer * 2 + (j >> 7)) * 64 * W1_S + c * W1_S + (j & 127);
                g_w1[off] = *(unsigned short*)&h;
            }
            {   // w2: [layer][j][c]
                int j = rem >> 6, c = rem & 63;
                __half h = __float2half_rn(w2g[idx]);
                int off = (layer * 2 + (j >> 7)) * 128 * W2_S + (j & 127) * W2_S + c;
                g_w2[off] = *(unsigned short*)&h;
            }
        }
        return;
    }
    int b = blockIdx.x;
    const float* p = prop + (size_t)b * NPIX;
    extern __shared__ unsigned dyn[];
    unsigned* skey = dyn;              // 25600 keys
    unsigned* hist = dyn + NPIX;       // 256
    __shared__ unsigned s_prefix;
    __shared__ int s_k;
    __shared__ int s_carry;
    __shared__ unsigned wtot[8];
    __shared__ int warp_sums[32];
    if (tid == 0) { s_prefix = 0u; s_k = KSEL; s_carry = 0; }
    for (int i = tid; i < NPIX; i += 1024) skey[i] = fkey(p[i]);
    __syncthreads();

    for (int pass = 3; pass >= 0; --pass) {
        int shift = pass * 8;
        if (tid < 256) hist[tid] = 0u;
        __syncthreads();
        unsigned prefix = s_prefix;
        unsigned highmask = (pass == 3) ? 0u : (0xFFFFFFFFu << (shift + 8));
        for (int i = tid; i < NPIX; i += 1024) {
            unsigned u = skey[i];
            if ((u & highmask) == prefix)
                atomicAdd(&hist[(u >> shift) & 255u], 1u);
        }
        __syncthreads();
        // ---- parallel suffix-sum digit selection (256 threads) ----
        int k = s_k;
        unsigned v = 0, h0 = 0;
        int l = tid & 31, w8 = tid >> 5;
        if (tid < 256) {
            v = hist[tid];
            h0 = v;
            #pragma unroll
            for (int off = 1; off < 32; off <<= 1) {
                unsigned t = __shfl_down_sync(0xffffffffu, v, off);
                if (l + off < 32) v += t;
            }
            if (l == 0) wtot[w8] = v;
        }
        __syncthreads();
        if (tid < 256) {
            unsigned suf = v;
            for (int q = w8 + 1; q < 8; ++q) suf += wtot[q];
            if ((int)suf >= k && (int)(suf - h0) < k) {
                s_prefix = prefix | ((unsigned)tid << shift);
                s_k = k - (int)(suf - h0);
            }
        }
        __syncthreads();
    }
    unsigned T = s_prefix;
    int ties = s_k;
    int lane = tid & 31, w = tid >> 5;
    for (int base = 0; base < NPIX; base += 1024) {
        int i = base + tid;
        unsigned u = skey[i];
        int gt = (u > T), eq = (u == T);
        unsigned ball = __ballot_sync(0xffffffffu, eq);
        int pre = __popc(ball & ((1u << lane) - 1u));
        if (lane == 0) warp_sums[w] = __popc(ball);
        __syncthreads();
        int woff = 0;
        for (int xw = 0; xw < w; ++xw) woff += warp_sums[xw];
        int rank = s_carry + woff + pre;
        g_flags[(size_t)b * NPIX + i] = (unsigned char)(gt || (eq && rank < ties));
        __syncthreads();
        if (tid == 0) {
            int tot = 0;
            for (int xw = 0; xw < 32; ++xw) tot += warp_sums[xw];
            s_carry += tot;
        }
        __syncthreads();
    }
}

// ---------------- kernel 2: fused LN + MLP, fp16, 32 tok/warp, occ 3 ----------
__global__ void __launch_bounds__(NTHR, 3)
main_kernel(const float* __restrict__ x,
            const float* __restrict__ lnscale, const float* __restrict__ lnbias,
            const float* __restrict__ b1g, const float* __restrict__ b2g,
            float* __restrict__ out) {
    extern __shared__ char sm[];
    float* sT  = (float*)(sm + OFF_T);
    unsigned* sB1h = (unsigned*)(sm + OFF_B1);
    float* sB2 = (float*)(sm + OFF_B2);
    float* sLS = (float*)(sm + OFF_LS);
    float* sLB = (float*)(sm + OFF_LB);
    int*   sFlag = (int*)(sm + OFF_FLAG);
    unsigned smem_base = (unsigned)__cvta_generic_to_shared(sm);

    int tid = threadIdx.x;
    int lane = tid & 31, w = tid >> 5;
    int tb = w * 32;                 // this warp's 32 tokens
    int b = blockIdx.y, n0 = blockIdx.x * TOKB;

    int r = lane >> 2;               // fragment row within 8
    int c2 = (lane & 3) * 2;         // fragment col pair
    int r15 = lane & 15;
    int colsel = ((lane >> 4) & 1) * 8;
    int row0a = tb + r,      row1a = row0a + 8;   // M-tile A
    int row0b = tb + 16 + r, row1b = row0b + 8;   // M-tile B

    // ---- stage chunk 0 weights (async, overlaps x-tile gmem loads) ----
    {
        const char* s1 = (const char*)g_w1;
        const char* s2 = (const char*)g_w2;
        unsigned dst = smem_base + OFF_W;
        for (int i = tid * 16; i < 64 * W1_S * 2; i += NTHR * 16) cp16(dst + i, s1 + i);
        for (int i = tid * 16; i < 128 * W2_S * 2; i += NTHR * 16) cp16(dst + 17408 + i, s2 + i);
        asm volatile("cp.async.commit_group;");
    }

    // ---- load x tile: sT[t][c], params, flags ----
    const float* xb = x + (size_t)b * CH * NPIX + n0;
    for (int i = tid; i < TOKB * CH; i += NTHR) {
        int t = i & (TOKB - 1);
        int c = i >> 7;
        sT[t * ST_S + c] = xb[(size_t)c * NPIX + t];
    }
    for (int i = tid; i < HID; i += NTHR)
        sB1h[i] = pack_h2(make_float2(b1g[2 * i], b1g[2 * i + 1]));
    if (tid < 2 * CH) {
        sB2[tid] = b2g[tid];
        sLS[tid] = lnscale[tid];
        sLB[tid] = lnbias[tid];
    }
    if (tid < TOKB) sFlag[tid] = g_flags[(size_t)b * NPIX + n0 + tid];
    __syncthreads();

    for (int layer = 0; layer < 2; ++layer) {
        // ---- LN stats: 1 lane per token (full 64-ch row) ----
        float mu, rs;
        {
            const float* rowp = sT + (tb + lane) * ST_S;
            float s = 0.f, s2 = 0.f;
            #pragma unroll
            for (int k = 0; k < 64; k += 4) {
                float4 v = *(const float4*)(rowp + k);
                s  += v.x + v.y + v.z + v.w;
                s2 += v.x * v.x + v.y * v.y + v.z * v.z + v.w * v.w;
            }
            mu = s * (1.f / 64.f);
            float var = s2 * (1.f / 64.f) - mu * mu;
            rs = rsqrtf(var + 1e-5f);
        }
        float mu0a = __shfl_sync(0xffffffffu, mu, r);
        float rs0a = __shfl_sync(0xffffffffu, rs, r);
        float mu1a = __shfl_sync(0xffffffffu, mu, r + 8);
        float rs1a = __shfl_sync(0xffffffffu, rs, r + 8);
        float mu0b = __shfl_sync(0xffffffffu, mu, r + 16);
        float rs0b = __shfl_sync(0xffffffffu, rs, r + 16);
        float mu1b = __shfl_sync(0xffffffffu, mu, r + 24);
        float rs1b = __shfl_sync(0xffffffffu, rs, r + 24);

        // ---- build GEMM1 A-fragments (Xn), fp16, two M-tiles ----
        unsigned aXa[16], aXb[16];
        #pragma unroll
        for (int kt = 0; kt < 4; ++kt) {
            int cA = kt * 16 + c2;
            float2 lsA = *(const float2*)(sLS + layer * 64 + cA);
            float2 lbA = *(const float2*)(sLB + layer * 64 + cA);
            float2 lsB = *(const float2*)(sLS + layer * 64 + cA + 8);
            float2 lbB = *(const float2*)(sLB + layer * 64 + cA + 8);
            float2 v;
            v = *(const float2*)(sT + row0a * ST_S + cA);
            v.x = (v.x - mu0a) * rs0a * lsA.x + lbA.x;
            v.y = (v.y - mu0a) * rs0a * lsA.y + lbA.y;
            aXa[kt * 4 + 0] = pack_h2(v);
            v = *(const float2*)(sT + row1a * ST_S + cA);
            v.x = (v.x - mu1a) * rs1a * lsA.x + lbA.x;
            v.y = (v.y - mu1a) * rs1a * lsA.y + lbA.y;
            aXa[kt * 4 + 1] = pack_h2(v);
            v = *(const float2*)(sT + row0a * ST_S + cA + 8);
            v.x = (v.x - mu0a) * rs0a * lsB.x + lbB.x;
            v.y = (v.y - mu0a) * rs0a * lsB.y + lbB.y;
            aXa[kt * 4 + 2] = pack_h2(v);
            v = *(const float2*)(sT + row1a * ST_S + cA + 8);
            v.x = (v.x - mu1a) * rs1a * lsB.x + lbB.x;
            v.y = (v.y - mu1a) * rs1a * lsB.y + lbB.y;
            aXa[kt * 4 + 3] = pack_h2(v);

            v = *(const float2*)(sT + row0b * ST_S + cA);
            v.x = (v.x - mu0b) * rs0b * lsA.x + lbA.x;
            v.y = (v.y - mu0b) * rs0b * lsA.y + lbA.y;
            aXb[kt * 4 + 0] = pack_h2(v);
            v = *(const float2*)(sT + row1b * ST_S + cA);
            v.x = (v.x - mu1b) * rs1b * lsA.x + lbA.x;
            v.y = (v.y - mu1b) * rs1b * lsA.y + lbA.y;
            aXb[kt * 4 + 1] = pack_h2(v);
            v = *(const float2*)(sT + row0b * ST_S + cA + 8);
            v.x = (v.x - mu0b) * rs0b * lsB.x + lbB.x;
            v.y = (v.y - mu0b) * rs0b * lsB.y + lbB.y;
            aXb[kt * 4 + 2] = pack_h2(v);
            v = *(const float2*)(sT + row1b * ST_S + cA + 8);
            v.x = (v.x - mu1b) * rs1b * lsB.x + lbB.x;
            v.y = (v.y - mu1b) * rs1b * lsB.y + lbB.y;
            aXb[kt * 4 + 3] = pack_h2(v);
        }

        float d2a[32], d2b[32];
        #pragma unroll
        for (int i = 0; i < 32; ++i) { d2a[i] = 0.f; d2b[i] = 0.f; }

        for (int jc = 0; jc < 2; ++jc) {
            int ch = layer * 2 + jc;
            unsigned wbase = smem_base + OFF_W;

            // ---- wait for this chunk's weights ----
            asm volatile("cp.async.wait_group 0;");
            __syncthreads();

            for (int jg = 0; jg < 8; ++jg) {
                // ---- GEMM1: two 16x16 M-tiles, K=64, shared B frags ----
                float d1a[8], d1b[8];
                #pragma unroll
                for (int i = 0; i < 8; ++i) { d1a[i] = 0.f; d1b[i] = 0.f; }
                #pragma unroll
                for (int kt = 0; kt < 4; ++kt) {
                    unsigned bh[4];
                    unsigned boff = (unsigned)((kt * 16 + r15) * W1_S + jg * 16 + colsel) * 2;
                    ldsm_x4t(bh, wbase + boff);
                    mma_f16(d1a,     aXa + kt * 4, bh[0], bh[1]);
                    mma_f16(d1b,     aXb + kt * 4, bh[0], bh[1]);
                    mma_f16(d1a + 4, aXa + kt * 4, bh[2], bh[3]);
                    mma_f16(d1b + 4, aXb + kt * 4, bh[2], bh[3]);
                }
                // ---- epilogue in h2: pack + bias + gelu -> GEMM2 A frags ----
                unsigned a2a[4], a2b[4];
                {
                    int j0 = jc * 128 + jg * 16;
                    int pb = (layer * HID + j0) >> 1;
                    unsigned b0 = sB1h[pb + (c2 >> 1)];
                    unsigned b8 = sB1h[pb + 4 + (c2 >> 1)];
                    __half2 b0h = *(__half2*)&b0, b8h = *(__half2*)&b8;
                    __half2 t; unsigned tu;
                    #define GEPI(dst, dd, bb) \
                        tu = pack_h2(make_float2((dd)[0], (dd)[1])); \
                        t = __hadd2(*(__half2*)&tu, bb); \
                        dst = gelu_h2(*(unsigned*)&t);
                    GEPI(a2a[0], d1a + 0, b0h); GEPI(a2a[1], d1a + 2, b0h);
                    GEPI(a2a[2], d1a + 4, b8h); GEPI(a2a[3], d1a + 6, b8h);
                    GEPI(a2b[0], d1b + 0, b0h); GEPI(a2b[1], d1b + 2, b0h);
                    GEPI(a2b[2], d1b + 4, b8h); GEPI(a2b[3], d1b + 6, b8h);
                    #undef GEPI
                }
                // ---- GEMM2 partial: k-tile = this jg, N=64, shared B frags ----
                #pragma unroll
                for (int np = 0; np < 4; ++np) {
                    unsigned bh[4];
                    unsigned boff = (unsigned)((jg * 16 + r15) * W2_S + np * 16 + colsel) * 2;
                    ldsm_x4t(bh, wbase + 17408 + boff);
                    mma_f16(d2a + np * 8,     a2a, bh[0], bh[1]);
                    mma_f16(d2b + np * 8,     a2b, bh[0], bh[1]);
                    mma_f16(d2a + np * 8 + 4, a2a, bh[2], bh[3]);
                    mma_f16(d2b + np * 8 + 4, a2b, bh[2], bh[3]);
                }
            }
            __syncthreads();   // all warps done with buffer

            // ---- stage next chunk (overlaps residual/LN across layers) ----
            if (ch < 3) {
                int nc = ch + 1;
                const char* s1 = (const char*)(g_w1 + nc * 64 * W1_S);
                const char* s2 = (const char*)(g_w2 + nc * 128 * W2_S);
                unsigned dst = smem_base + OFF_W;
                for (int i = tid * 16; i < 64 * W1_S * 2; i += NTHR * 16) cp16(dst + i, s1 + i);
                for (int i = tid * 16; i < 128 * W2_S * 2; i += NTHR * 16) cp16(dst + 17408 + i, s2 + i);
                asm volatile("cp.async.commit_group;");
            }
        }

        // ---- gated residual add into sT (warp-local rows) ----
        {
            int f0a = sFlag[row0a], f1a = sFlag[row1a];
            int f0b = sFlag[row0b], f1b = sFlag[row1b];
            #pragma unroll
            for (int nt = 0; nt < 8; ++nt) {
                int c0 = nt * 8 + c2;
                float2 bv = *(const float2*)(sB2 + layer * 64 + c0);
                if (f0a) {
                    sT[row0a * ST_S + c0]     += d2a[nt * 4 + 0] + bv.x;
                    sT[row0a * ST_S + c0 + 1] += d2a[nt * 4 + 1] + bv.y;
                }
                if (f1a) {
                    sT[row1a * ST_S + c0]     += d2a[nt * 4 + 2] + bv.x;
                    sT[row1a * ST_S + c0 + 1] += d2a[nt * 4 + 3] + bv.y;
                }
                if (f0b) {
                    sT[row0b * ST_S + c0]     += d2b[nt * 4 + 0] + bv.x;
                    sT[row0b * ST_S + c0 + 1] += d2b[nt * 4 + 1] + bv.y;
                }
                if (f1b) {
                    sT[row1b * ST_S + c0]     += d2b[nt * 4 + 2] + bv.x;
                    sT[row1b * ST_S + c0 + 1] += d2b[nt * 4 + 3] + bv.y;
                }
            }
        }
        __syncwarp();
    }

    // ---- store tile ----
    __syncthreads();
    float* ob = out + (size_t)b * CH * NPIX + n0;
    for (int i = tid; i < TOKB * CH; i += NTHR) {
        int t = i & (TOKB - 1);
        int c = i >> 7;
        ob[(size_t)c * NPIX + t] = sT[t * ST_S + c];
    }
}

// ---------------- launch ----------------
extern "C" void kernel_launch(void* const* d_in, const int* in_sizes, int n_in,
                              void* d_out, int out_size) {
    const float* x    = (const float*)d_in[0];
    const float* prop = (const float*)d_in[1];
    const float* lns  = (const float*)d_in[2];
    const float* lnb  = (const float*)d_in[3];
    const float* w1   = (const float*)d_in[4];
    const float* b1   = (const float*)d_in[5];
    const float* w2   = (const float*)d_in[6];
    const float* b2   = (const float*)d_in[7];
    float* out = (float*)d_out;

    cudaFuncSetAttribute(main_kernel, cudaFuncAttributeMaxDynamicSharedMemorySize, SMEM_BYTES);
    int sel_smem = (NPIX + 260) * 4;
    cudaFuncSetAttribute(select_flags_kernel, cudaFuncAttributeMaxDynamicSharedMemorySize, sel_smem);

    select_flags_kernel<<<BATCH + 2, 1024, sel_smem>>>(prop, w1, w2);
    dim3 grid(NPIX / TOKB, BATCH);
    main_kernel<<<grid, NTHR, SMEM_BYTES>>>(x, lns, lnb, b1, b2, out);
}

// round 13
// speedup vs baseline: 2.0141x; 1.0300x over previous
#include <cuda_runtime.h>
#include <cuda_fp16.h>
#include <math.h>

#define BATCH 16
#define CH    64
#define NPIX  25600          // 160*160
#define HID   256
#define KSEL  20480          // ceil(25600*0.8)
#define TOKB  128            // tokens per block
#define NTHR  128            // 4 warps x 32 tokens each

#define ST_S  68             // sT fp32 row stride (272B)
#define W1_S  136            // fp16 elements per row (272B), chunk rows=64
#define W2_S  72             // fp16 elements per row (144B), chunk rows=128

// smem byte offsets (main kernel) -- SINGLE weight buffer, occupancy 3
#define OFF_T    0            // 128*68*4  = 34816
#define OFF_W    34816        // one chunk buffer 35840 (W1 17408 + W2 18432)
#define OFF_B1   70656        // 256 u32 (h2-packed bias1)
#define OFF_B2   71680        // 2*64*4 = 512
#define OFF_LS   72192        // 512
#define OFF_LB   72704        // 512
#define OFF_FLAG 73216        // 128*4 = 512
#define SMEM_BYTES 73728      // x3 CTAs = 221184 <= 227KB

// ---------------- static scratch ----------------
__device__ unsigned      g_thresh[BATCH];
__device__ int           g_ties[BATCH];
__device__ unsigned char g_flags[BATCH * NPIX];
// pre-converted fp16 weights in smem tile layout (chunk = layer*2 + jc)
__device__ __align__(16) unsigned short g_w1[4 * 64 * W1_S];
__device__ __align__(16) unsigned short g_w2[4 * 128 * W2_S];

__device__ __forceinline__ unsigned fkey(float f) {
    unsigned u = __float_as_uint(f);
    return (u & 0x80000000u) ? ~u : (u | 0x80000000u);
}

__device__ __forceinline__ unsigned pack_h2(float2 v) {
    __half2 h = __float22half2_rn(v);
    return *(unsigned*)&h;
}

// gelu on a packed half2 (tanh approximation, all-fp16 math)
__device__ __forceinline__ unsigned gelu_h2(unsigned vu) {
    __half2 v = *(__half2*)&vu;
    const __half2 k0  = __floats2half2_rn(0.7978845608f, 0.7978845608f);
    const __half2 k01 = __floats2half2_rn(0.0356774081f, 0.0356774081f);  // k0*0.044715
    const __half2 hf  = __floats2half2_rn(0.5f, 0.5f);
    __half2 u = __hmul2(v, v);
    __half2 w = __hmul2(u, v);
    __half2 inner = __hfma2(w, k01, __hmul2(v, k0));
    unsigned tin = *(unsigned*)&inner, tout;
    asm("tanh.approx.f16x2 %0, %1;" : "=r"(tout) : "r"(tin));
    __half2 t = *(__half2*)&tout;
    __half2 hv = __hmul2(v, hf);
    __half2 res = __hfma2(hv, t, hv);
    return *(unsigned*)&res;
}

__device__ __forceinline__ void ldsm_x4t(unsigned* r, unsigned addr) {
    asm volatile("ldmatrix.sync.aligned.m8n8.x4.trans.shared.b16 {%0,%1,%2,%3}, [%4];"
                 : "=r"(r[0]), "=r"(r[1]), "=r"(r[2]), "=r"(r[3]) : "r"(addr));
}
__device__ __forceinline__ void mma_f16(float* d, const unsigned* a, unsigned b0, unsigned b1) {
    asm volatile("mma.sync.aligned.m16n8k16.row.col.f32.f16.f16.f32 "
                 "{%0,%1,%2,%3}, {%4,%5,%6,%7}, {%8,%9}, {%0,%1,%2,%3};"
                 : "+f"(d[0]), "+f"(d[1]), "+f"(d[2]), "+f"(d[3])
                 : "r"(a[0]), "r"(a[1]), "r"(a[2]), "r"(a[3]), "r"(b0), "r"(b1));
}
__device__ __forceinline__ void cp16(unsigned dst, const void* src) {
    asm volatile("cp.async.cg.shared.global [%0], [%1], 16;" :: "r"(dst), "l"(src));
}

// ---------------- kernel 1: fused prep + per-batch radix select + flags ----------------
__global__ void select_flags_kernel(const float* __restrict__ prop,
                                    const float* __restrict__ w1g, const float* __restrict__ w2g) {
    int tid = threadIdx.x;
    if (blockIdx.x >= BATCH) {
        // ---- prep: pre-convert weights to fp16 smem-tile layout ----
        int base = (blockIdx.x - BATCH) * 16384;
        #pragma unroll 4
        for (int q = 0; q < 16; ++q) {
            int idx = base + q * 1024 + tid;
            int layer = idx >> 14;
            int rem = idx & 16383;
            {   // w1: [layer][c][j]
                int c = rem >> 8, j = rem & 255;
                __half h = __float2half_rn(w1g[idx]);
                int off = (layer * 2 + (j >> 7)) * 64 * W1_S + c * W1_S + (j & 127);
                g_w1[off] = *(unsigned short*)&h;
            }
            {   // w2: [layer][j][c]
                int j = rem >> 6, c = rem & 63;
                __half h = __float2half_rn(w2g[idx]);
                int off = (layer * 2 + (j >> 7)) * 128 * W2_S + (j & 127) * W2_S + c;
                g_w2[off] = *(unsigned short*)&h;
            }
        }
        return;
    }
    int b = blockIdx.x;
    const float* p = prop + (size_t)b * NPIX;
    extern __shared__ unsigned dyn[];
    unsigned* skey = dyn;              // 25600 keys
    unsigned* hist = dyn + NPIX;       // 256
    __shared__ unsigned s_prefix;
    __shared__ int s_k;
    __shared__ int s_carry;
    __shared__ unsigned wtot[8];
    __shared__ int warp_sums[32];
    if (tid == 0) { s_prefix = 0u; s_k = KSEL; s_carry = 0; }
    for (int i = tid; i < NPIX; i += 1024) skey[i] = fkey(p[i]);
    __syncthreads();

    for (int pass = 3; pass >= 0; --pass) {
        int shift = pass * 8;
        if (tid < 256) hist[tid] = 0u;
        __syncthreads();
        unsigned prefix = s_prefix;
        unsigned highmask = (pass == 3) ? 0u : (0xFFFFFFFFu << (shift + 8));
        for (int i = tid; i < NPIX; i += 1024) {
            unsigned u = skey[i];
            if ((u & highmask) == prefix)
                atomicAdd(&hist[(u >> shift) & 255u], 1u);
        }
        __syncthreads();
        // ---- parallel suffix-sum digit selection (256 threads) ----
        int k = s_k;
        unsigned v = 0, h0 = 0;
        int l = tid & 31, w8 = tid >> 5;
        if (tid < 256) {
            v = hist[tid];
            h0 = v;
            #pragma unroll
            for (int off = 1; off < 32; off <<= 1) {
                unsigned t = __shfl_down_sync(0xffffffffu, v, off);
                if (l + off < 32) v += t;
            }
            if (l == 0) wtot[w8] = v;
        }
        __syncthreads();
        if (tid < 256) {
            unsigned suf = v;
            for (int q = w8 + 1; q < 8; ++q) suf += wtot[q];
            if ((int)suf >= k && (int)(suf - h0) < k) {
                s_prefix = prefix | ((unsigned)tid << shift);
                s_k = k - (int)(suf - h0);
            }
        }
        __syncthreads();
    }
    unsigned T = s_prefix;
    int ties = s_k;
    int lane = tid & 31, w = tid >> 5;
    for (int base = 0; base < NPIX; base += 1024) {
        int i = base + tid;
        unsigned u = skey[i];
        int gt = (u > T), eq = (u == T);
        unsigned ball = __ballot_sync(0xffffffffu, eq);
        int pre = __popc(ball & ((1u << lane) - 1u));
        if (lane == 0) warp_sums[w] = __popc(ball);
        __syncthreads();
        int woff = 0;
        for (int xw = 0; xw < w; ++xw) woff += warp_sums[xw];
        int rank = s_carry + woff + pre;
        g_flags[(size_t)b * NPIX + i] = (unsigned char)(gt || (eq && rank < ties));
        __syncthreads();
        if (tid == 0) {
            int tot = 0;
            for (int xw = 0; xw < 32; ++xw) tot += warp_sums[xw];
            s_carry += tot;
        }
        __syncthreads();
    }
}

// ---------------- kernel 2: fused LN + MLP, fp16, epilogue-lag pipeline, occ 3 ----------
__global__ void __launch_bounds__(NTHR, 3)
main_kernel(const float* __restrict__ x,
            const float* __restrict__ lnscale, const float* __restrict__ lnbias,
            const float* __restrict__ b1g, const float* __restrict__ b2g,
            float* __restrict__ out) {
    extern __shared__ char sm[];
    float* sT  = (float*)(sm + OFF_T);
    unsigned* sB1h = (unsigned*)(sm + OFF_B1);
    float* sB2 = (float*)(sm + OFF_B2);
    float* sLS = (float*)(sm + OFF_LS);
    float* sLB = (float*)(sm + OFF_LB);
    int*   sFlag = (int*)(sm + OFF_FLAG);
    unsigned smem_base = (unsigned)__cvta_generic_to_shared(sm);

    int tid = threadIdx.x;
    int lane = tid & 31, w = tid >> 5;
    int tb = w * 32;                 // this warp's 32 tokens
    int b = blockIdx.y, n0 = blockIdx.x * TOKB;

    int r = lane >> 2;               // fragment row within 8
    int c2 = (lane & 3) * 2;         // fragment col pair
    int r15 = lane & 15;
    int colsel = ((lane >> 4) & 1) * 8;
    int row0a = tb + r,      row1a = row0a + 8;   // M-tile A
    int row0b = tb + 16 + r, row1b = row0b + 8;   // M-tile B

    // ---- stage chunk 0 weights (async, overlaps x-tile gmem loads) ----
    {
        const char* s1 = (const char*)g_w1;
        const char* s2 = (const char*)g_w2;
        unsigned dst = smem_base + OFF_W;
        for (int i = tid * 16; i < 64 * W1_S * 2; i += NTHR * 16) cp16(dst + i, s1 + i);
        for (int i = tid * 16; i < 128 * W2_S * 2; i += NTHR * 16) cp16(dst + 17408 + i, s2 + i);
        asm volatile("cp.async.commit_group;");
    }

    // ---- load x tile: sT[t][c], params, flags ----
    const float* xb = x + (size_t)b * CH * NPIX + n0;
    for (int i = tid; i < TOKB * CH; i += NTHR) {
        int t = i & (TOKB - 1);
        int c = i >> 7;
        sT[t * ST_S + c] = xb[(size_t)c * NPIX + t];
    }
    for (int i = tid; i < HID; i += NTHR)
        sB1h[i] = pack_h2(make_float2(b1g[2 * i], b1g[2 * i + 1]));
    if (tid < 2 * CH) {
        sB2[tid] = b2g[tid];
        sLS[tid] = lnscale[tid];
        sLB[tid] = lnbias[tid];
    }
    if (tid < TOKB) sFlag[tid] = g_flags[(size_t)b * NPIX + n0 + tid];
    __syncthreads();

    for (int layer = 0; layer < 2; ++layer) {
        // ---- LN stats: 1 lane per token (full 64-ch row) ----
        float mu, rs;
        {
            const float* rowp = sT + (tb + lane) * ST_S;
            float s = 0.f, s2 = 0.f;
            #pragma unroll
            for (int k = 0; k < 64; k += 4) {
                float4 v = *(const float4*)(rowp + k);
                s  += v.x + v.y + v.z + v.w;
                s2 += v.x * v.x + v.y * v.y + v.z * v.z + v.w * v.w;
            }
            mu = s * (1.f / 64.f);
            float var = s2 * (1.f / 64.f) - mu * mu;
            rs = rsqrtf(var + 1e-5f);
        }
        float mu0a = __shfl_sync(0xffffffffu, mu, r);
        float rs0a = __shfl_sync(0xffffffffu, rs, r);
        float mu1a = __shfl_sync(0xffffffffu, mu, r + 8);
        float rs1a = __shfl_sync(0xffffffffu, rs, r + 8);
        float mu0b = __shfl_sync(0xffffffffu, mu, r + 16);
        float rs0b = __shfl_sync(0xffffffffu, rs, r + 16);
        float mu1b = __shfl_sync(0xffffffffu, mu, r + 24);
        float rs1b = __shfl_sync(0xffffffffu, rs, r + 24);

        // ---- build GEMM1 A-fragments (Xn), fp16, two M-tiles ----
        unsigned aXa[16], aXb[16];
        #pragma unroll
        for (int kt = 0; kt < 4; ++kt) {
            int cA = kt * 16 + c2;
            float2 lsA = *(const float2*)(sLS + layer * 64 + cA);
            float2 lbA = *(const float2*)(sLB + layer * 64 + cA);
            float2 lsB = *(const float2*)(sLS + layer * 64 + cA + 8);
            float2 lbB = *(const float2*)(sLB + layer * 64 + cA + 8);
            float2 v;
            v = *(const float2*)(sT + row0a * ST_S + cA);
            v.x = (v.x - mu0a) * rs0a * lsA.x + lbA.x;
            v.y = (v.y - mu0a) * rs0a * lsA.y + lbA.y;
            aXa[kt * 4 + 0] = pack_h2(v);
            v = *(const float2*)(sT + row1a * ST_S + cA);
            v.x = (v.x - mu1a) * rs1a * lsA.x + lbA.x;
            v.y = (v.y - mu1a) * rs1a * lsA.y + lbA.y;
            aXa[kt * 4 + 1] = pack_h2(v);
            v = *(const float2*)(sT + row0a * ST_S + cA + 8);
            v.x = (v.x - mu0a) * rs0a * lsB.x + lbB.x;
            v.y = (v.y - mu0a) * rs0a * lsB.y + lbB.y;
            aXa[kt * 4 + 2] = pack_h2(v);
            v = *(const float2*)(sT + row1a * ST_S + cA + 8);
            v.x = (v.x - mu1a) * rs1a * lsB.x + lbB.x;
            v.y = (v.y - mu1a) * rs1a * lsB.y + lbB.y;
            aXa[kt * 4 + 3] = pack_h2(v);

            v = *(const float2*)(sT + row0b * ST_S + cA);
            v.x = (v.x - mu0b) * rs0b * lsA.x + lbA.x;
            v.y = (v.y - mu0b) * rs0b * lsA.y + lbA.y;
            aXb[kt * 4 + 0] = pack_h2(v);
            v = *(const float2*)(sT + row1b * ST_S + cA);
            v.x = (v.x - mu1b) * rs1b * lsA.x + lbA.x;
            v.y = (v.y - mu1b) * rs1b * lsA.y + lbA.y;
            aXb[kt * 4 + 1] = pack_h2(v);
            v = *(const float2*)(sT + row0b * ST_S + cA + 8);
            v.x = (v.x - mu0b) * rs0b * lsB.x + lbB.x;
            v.y = (v.y - mu0b) * rs0b * lsB.y + lbB.y;
            aXb[kt * 4 + 2] = pack_h2(v);
            v = *(const float2*)(sT + row1b * ST_S + cA + 8);
            v.x = (v.x - mu1b) * rs1b * lsB.x + lbB.x;
            v.y = (v.y - mu1b) * rs1b * lsB.y + lbB.y;
            aXb[kt * 4 + 3] = pack_h2(v);
        }

        float d2a[32], d2b[32];
        #pragma unroll
        for (int i = 0; i < 32; ++i) { d2a[i] = 0.f; d2b[i] = 0.f; }

        for (int jc = 0; jc < 2; ++jc) {
            int ch = layer * 2 + jc;
            unsigned wbase = smem_base + OFF_W;

            // ---- wait for this chunk's weights ----
            asm volatile("cp.async.wait_group 0;");
            __syncthreads();

            // ---- epilogue-lag pipeline: G1(jg) ; G2(a2 of jg-1) ; epi(jg)->a2 ----
            unsigned a2a[4], a2b[4];
            #pragma unroll
            for (int jg = 0; jg < 8; ++jg) {
                // GEMM1(jg): two 16x16 M-tiles, K=64, shared B frags
                float d1a[8], d1b[8];
                #pragma unroll
                for (int i = 0; i < 8; ++i) { d1a[i] = 0.f; d1b[i] = 0.f; }
                #pragma unroll
                for (int kt = 0; kt < 4; ++kt) {
                    unsigned bh[4];
                    unsigned boff = (unsigned)((kt * 16 + r15) * W1_S + jg * 16 + colsel) * 2;
                    ldsm_x4t(bh, wbase + boff);
                    mma_f16(d1a,     aXa + kt * 4, bh[0], bh[1]);
                    mma_f16(d1b,     aXb + kt * 4, bh[0], bh[1]);
                    mma_f16(d1a + 4, aXa + kt * 4, bh[2], bh[3]);
                    mma_f16(d1b + 4, aXb + kt * 4, bh[2], bh[3]);
                }
                // GEMM2(jg-1): uses a2 computed LAST iteration (RAW long satisfied)
                if (jg > 0) {
                    int jp = jg - 1;
                    #pragma unroll
                    for (int np = 0; np < 4; ++np) {
                        unsigned bh[4];
                        unsigned boff = (unsigned)((jp * 16 + r15) * W2_S + np * 16 + colsel) * 2;
                        ldsm_x4t(bh, wbase + 17408 + boff);
                        mma_f16(d2a + np * 8,     a2a, bh[0], bh[1]);
                        mma_f16(d2b + np * 8,     a2b, bh[0], bh[1]);
                        mma_f16(d2a + np * 8 + 4, a2a, bh[2], bh[3]);
                        mma_f16(d2b + np * 8 + 4, a2b, bh[2], bh[3]);
                    }
                }
                // epilogue(jg): pack + bias + gelu -> a2 (consumed next iteration)
                {
                    int j0 = jc * 128 + jg * 16;
                    int pb = (layer * HID + j0) >> 1;
                    unsigned b0 = sB1h[pb + (c2 >> 1)];
                    unsigned b8 = sB1h[pb + 4 + (c2 >> 1)];
                    __half2 b0h = *(__half2*)&b0, b8h = *(__half2*)&b8;
                    __half2 t; unsigned tu;
                    #define GEPI(dst, dd, bb) \
                        tu = pack_h2(make_float2((dd)[0], (dd)[1])); \
                        t = __hadd2(*(__half2*)&tu, bb); \
                        dst = gelu_h2(*(unsigned*)&t);
                    GEPI(a2a[0], d1a + 0, b0h); GEPI(a2a[1], d1a + 2, b0h);
                    GEPI(a2a[2], d1a + 4, b8h); GEPI(a2a[3], d1a + 6, b8h);
                    GEPI(a2b[0], d1b + 0, b0h); GEPI(a2b[1], d1b + 2, b0h);
                    GEPI(a2b[2], d1b + 4, b8h); GEPI(a2b[3], d1b + 6, b8h);
                    #undef GEPI
                }
            }
            // drain: GEMM2 for jg=7 (must run before buffer is overwritten)
            #pragma unroll
            for (int np = 0; np < 4; ++np) {
                unsigned bh[4];
                unsigned boff = (unsigned)((7 * 16 + r15) * W2_S + np * 16 + colsel) * 2;
                ldsm_x4t(bh, wbase + 17408 + boff);
                mma_f16(d2a + np * 8,     a2a, bh[0], bh[1]);
                mma_f16(d2b + np * 8,     a2b, bh[0], bh[1]);
                mma_f16(d2a + np * 8 + 4, a2a, bh[2], bh[3]);
                mma_f16(d2b + np * 8 + 4, a2b, bh[2], bh[3]);
            }
            __syncthreads();   // all warps done with buffer

            // ---- stage next chunk (overlaps residual/LN across layers) ----
            if (ch < 3) {
                int nc = ch + 1;
                const char* s1 = (const char*)(g_w1 + nc * 64 * W1_S);
                const char* s2 = (const char*)(g_w2 + nc * 128 * W2_S);
                unsigned dst = smem_base + OFF_W;
                for (int i = tid * 16; i < 64 * W1_S * 2; i += NTHR * 16) cp16(dst + i, s1 + i);
                for (int i = tid * 16; i < 128 * W2_S * 2; i += NTHR * 16) cp16(dst + 17408 + i, s2 + i);
                asm volatile("cp.async.commit_group;");
            }
        }

        // ---- gated residual add into sT (warp-local rows) ----
        {
            int f0a = sFlag[row0a], f1a = sFlag[row1a];
            int f0b = sFlag[row0b], f1b = sFlag[row1b];
            #pragma unroll
            for (int nt = 0; nt < 8; ++nt) {
                int c0 = nt * 8 + c2;
                float2 bv = *(const float2*)(sB2 + layer * 64 + c0);
                if (f0a) {
                    sT[row0a * ST_S + c0]     += d2a[nt * 4 + 0] + bv.x;
                    sT[row0a * ST_S + c0 + 1] += d2a[nt * 4 + 1] + bv.y;
                }
                if (f1a) {
                    sT[row1a * ST_S + c0]     += d2a[nt * 4 + 2] + bv.x;
                    sT[row1a * ST_S + c0 + 1] += d2a[nt * 4 + 3] + bv.y;
                }
                if (f0b) {
                    sT[row0b * ST_S + c0]     += d2b[nt * 4 + 0] + bv.x;
                    sT[row0b * ST_S + c0 + 1] += d2b[nt * 4 + 1] + bv.y;
                }
                if (f1b) {
                    sT[row1b * ST_S + c0]     += d2b[nt * 4 + 2] + bv.x;
                    sT[row1b * ST_S + c0 + 1] += d2b[nt * 4 + 3] + bv.y;
                }
            }
        }
        __syncwarp();
    }

    // ---- store tile ----
    __syncthreads();
    float* ob = out + (size_t)b * CH * NPIX + n0;
    for (int i = tid; i < TOKB * CH; i += NTHR) {
        int t = i & (TOKB - 1);
        int c = i >> 7;
        ob[(size_t)c * NPIX + t] = sT[t * ST_S + c];
    }
}

// ---------------- launch ----------------
extern "C" void kernel_launch(void* const* d_in, const int* in_sizes, int n_in,
                              void* d_out, int out_size) {
    const float* x    = (const float*)d_in[0];
    const float* prop = (const float*)d_in[1];
    const float* lns  = (const float*)d_in[2];
    const float* lnb  = (const float*)d_in[3];
    const float* w1   = (const float*)d_in[4];
    const float* b1   = (const float*)d_in[5];
    const float* w2   = (const float*)d_in[6];
    const float* b2   = (const float*)d_in[7];
    float* out = (float*)d_out;

    cudaFuncSetAttribute(main_kernel, cudaFuncAttributeMaxDynamicSharedMemorySize, SMEM_BYTES);
    int sel_smem = (NPIX + 260) * 4;
    cudaFuncSetAttribute(select_flags_kernel, cudaFuncAttributeMaxDynamicSharedMemorySize, sel_smem);

    select_flags_kernel<<<BATCH + 2, 1024, sel_smem>>>(prop, w1, w2);
    dim3 grid(NPIX / TOKB, BATCH);
    main_kernel<<<grid, NTHR, SMEM_BYTES>>>(x, lns, lnb, b1, b2, out);
}

// round 14
// speedup vs baseline: 2.0254x; 1.0056x over previous
#include <cuda_runtime.h>
#include <cuda_fp16.h>
#include <math.h>

#define BATCH 16
#define CH    64
#define NPIX  25600          // 160*160
#define HID   256
#define KSEL  20480          // ceil(25600*0.8); divisible by 128
#define TOKB  128            // tokens per block
#define NTHR  128            // 4 warps x 32 tokens each

#define ST_S  68             // sT fp32 row stride (272B)
#define W1_S  136            // fp16 elements per row (272B), chunk rows=64
#define W2_S  72             // fp16 elements per row (144B), chunk rows=128

// smem byte offsets (main kernel) -- SINGLE weight buffer, occupancy 3
#define OFF_T    0            // 128*68*4  = 34816
#define OFF_W    34816        // one chunk buffer 35840 (W1 17408 + W2 18432)
#define OFF_B1   70656        // 256 u32 (h2-packed bias1)
#define OFF_B2   71680        // 2*64*4 = 512
#define OFF_LS   72192        // 512
#define OFF_LB   72704        // 512
#define OFF_IDX  73216        // 128*4 = 512 (gathered token indices)
#define SMEM_BYTES 73728      // x3 CTAs = 221184 <= 227KB

// ---------------- static scratch ----------------
__device__ unsigned      g_thresh[BATCH];
__device__ int           g_ties[BATCH];
__device__ unsigned char g_flags[BATCH * NPIX];
__device__ int           g_idx[BATCH * KSEL];
// pre-converted fp16 weights in smem tile layout (chunk = layer*2 + jc)
__device__ __align__(16) unsigned short g_w1[4 * 64 * W1_S];
__device__ __align__(16) unsigned short g_w2[4 * 128 * W2_S];

__device__ __forceinline__ unsigned fkey(float f) {
    unsigned u = __float_as_uint(f);
    return (u & 0x80000000u) ? ~u : (u | 0x80000000u);
}

__device__ __forceinline__ unsigned pack_h2(float2 v) {
    __half2 h = __float22half2_rn(v);
    return *(unsigned*)&h;
}

// gelu on a packed half2 (tanh approximation, all-fp16 math)
__device__ __forceinline__ unsigned gelu_h2(unsigned vu) {
    __half2 v = *(__half2*)&vu;
    const __half2 k0  = __floats2half2_rn(0.7978845608f, 0.7978845608f);
    const __half2 k01 = __floats2half2_rn(0.0356774081f, 0.0356774081f);  // k0*0.044715
    const __half2 hf  = __floats2half2_rn(0.5f, 0.5f);
    __half2 u = __hmul2(v, v);
    __half2 w = __hmul2(u, v);
    __half2 inner = __hfma2(w, k01, __hmul2(v, k0));
    unsigned tin = *(unsigned*)&inner, tout;
    asm("tanh.approx.f16x2 %0, %1;" : "=r"(tout) : "r"(tin));
    __half2 t = *(__half2*)&tout;
    __half2 hv = __hmul2(v, hf);
    __half2 res = __hfma2(hv, t, hv);
    return *(unsigned*)&res;
}

__device__ __forceinline__ void ldsm_x4t(unsigned* r, unsigned addr) {
    asm volatile("ldmatrix.sync.aligned.m8n8.x4.trans.shared.b16 {%0,%1,%2,%3}, [%4];"
                 : "=r"(r[0]), "=r"(r[1]), "=r"(r[2]), "=r"(r[3]) : "r"(addr));
}
__device__ __forceinline__ void mma_f16(float* d, const unsigned* a, unsigned b0, unsigned b1) {
    asm volatile("mma.sync.aligned.m16n8k16.row.col.f32.f16.f16.f32 "
                 "{%0,%1,%2,%3}, {%4,%5,%6,%7}, {%8,%9}, {%0,%1,%2,%3};"
                 : "+f"(d[0]), "+f"(d[1]), "+f"(d[2]), "+f"(d[3])
                 : "r"(a[0]), "r"(a[1]), "r"(a[2]), "r"(a[3]), "r"(b0), "r"(b1));
}
__device__ __forceinline__ void cp16(unsigned dst, const void* src) {
    asm volatile("cp.async.cg.shared.global [%0], [%1], 16;" :: "r"(dst), "l"(src));
}

// ---------------- kernel 1: fused prep + radix select + flags + index compaction ----
__global__ void select_flags_kernel(const float* __restrict__ prop,
                                    const float* __restrict__ w1g, const float* __restrict__ w2g) {
    int tid = threadIdx.x;
    if (blockIdx.x >= BATCH) {
        // ---- prep: pre-convert weights to fp16 smem-tile layout ----
        int base = (blockIdx.x - BATCH) * 16384;
        #pragma unroll 4
        for (int q = 0; q < 16; ++q) {
            int idx = base + q * 1024 + tid;
            int layer = idx >> 14;
            int rem = idx & 16383;
            {   // w1: [layer][c][j]
                int c = rem >> 8, j = rem & 255;
                __half h = __float2half_rn(w1g[idx]);
                int off = (layer * 2 + (j >> 7)) * 64 * W1_S + c * W1_S + (j & 127);
                g_w1[off] = *(unsigned short*)&h;
            }
            {   // w2: [layer][j][c]
                int j = rem >> 6, c = rem & 63;
                __half h = __float2half_rn(w2g[idx]);
                int off = (layer * 2 + (j >> 7)) * 128 * W2_S + (j & 127) * W2_S + c;
                g_w2[off] = *(unsigned short*)&h;
            }
        }
        return;
    }
    int b = blockIdx.x;
    const float* p = prop + (size_t)b * NPIX;
    extern __shared__ unsigned dyn[];
    unsigned* skey = dyn;              // 25600 keys
    unsigned* hist = dyn + NPIX;       // 256
    __shared__ unsigned s_prefix;
    __shared__ int s_k;
    __shared__ int s_carry;            // eq rank carry
    __shared__ int s_scarry;           // selected-position carry
    __shared__ unsigned wtot[8];
    __shared__ int wsF[32], wsS[32];
    if (tid == 0) { s_prefix = 0u; s_k = KSEL; s_carry = 0; s_scarry = 0; }
    for (int i = tid; i < NPIX; i += 1024) skey[i] = fkey(p[i]);
    __syncthreads();

    for (int pass = 3; pass >= 0; --pass) {
        int shift = pass * 8;
        if (tid < 256) hist[tid] = 0u;
        __syncthreads();
        unsigned prefix = s_prefix;
        unsigned highmask = (pass == 3) ? 0u : (0xFFFFFFFFu << (shift + 8));
        for (int i = tid; i < NPIX; i += 1024) {
            unsigned u = skey[i];
            if ((u & highmask) == prefix)
                atomicAdd(&hist[(u >> shift) & 255u], 1u);
        }
        __syncthreads();
        // ---- parallel suffix-sum digit selection (256 threads) ----
        int k = s_k;
        unsigned v = 0, h0 = 0;
        int l = tid & 31, w8 = tid >> 5;
        if (tid < 256) {
            v = hist[tid];
            h0 = v;
            #pragma unroll
            for (int off = 1; off < 32; off <<= 1) {
                unsigned t = __shfl_down_sync(0xffffffffu, v, off);
                if (l + off < 32) v += t;
            }
            if (l == 0) wtot[w8] = v;
        }
        __syncthreads();
        if (tid < 256) {
            unsigned suf = v;
            for (int q = w8 + 1; q < 8; ++q) suf += wtot[q];
            if ((int)suf >= k && (int)(suf - h0) < k) {
                s_prefix = prefix | ((unsigned)tid << shift);
                s_k = k - (int)(suf - h0);
            }
        }
        __syncthreads();
    }
    unsigned T = s_prefix;
    int ties = s_k;
    int lane = tid & 31, w = tid >> 5;
    for (int base = 0; base < NPIX; base += 1024) {
        int i = base + tid;
        unsigned u = skey[i];
        int gt = (u > T), eq = (u == T);
        unsigned ballF = __ballot_sync(0xffffffffu, eq);
        int preF = __popc(ballF & ((1u << lane) - 1u));
        if (lane == 0) wsF[w] = __popc(ballF);
        __syncthreads();
        int woffF = 0;
        for (int xw = 0; xw < w; ++xw) woffF += wsF[xw];
        int rank = s_carry + woffF + preF;
        int sel = gt || (eq && rank < ties);
        unsigned ballS = __ballot_sync(0xffffffffu, sel);
        int preS = __popc(ballS & ((1u << lane) - 1u));
        if (lane == 0) wsS[w] = __popc(ballS);
        __syncthreads();
        int woffS = 0;
        for (int xw = 0; xw < w; ++xw) woffS += wsS[xw];
        int pos = s_scarry + woffS + preS;
        g_flags[(size_t)b * NPIX + i] = (unsigned char)sel;
        if (sel) g_idx[(size_t)b * KSEL + pos] = i;
        __syncthreads();
        if (tid == 0) {
            int totF = 0, totS = 0;
            for (int xw = 0; xw < 32; ++xw) { totF += wsF[xw]; totS += wsS[xw]; }
            s_carry += totF;
            s_scarry += totS;
        }
        __syncthreads();
    }
}

// ---------------- kernel 1b: pass-through copy for unselected tokens ----------------
__global__ void copy_kernel(const float* __restrict__ x, float* __restrict__ out) {
    int b = blockIdx.y;
    int i = blockIdx.x * 128 + threadIdx.x;
    if (g_flags[(size_t)b * NPIX + i]) return;
    const float* xb = x + (size_t)b * CH * NPIX + i;
    float* ob = out + (size_t)b * CH * NPIX + i;
    #pragma unroll 8
    for (int c = 0; c < CH; ++c)
        ob[(size_t)c * NPIX] = xb[(size_t)c * NPIX];
}

// ---------------- kernel 2: fused LN + MLP over COMPACTED selected tokens ----------
__global__ void __launch_bounds__(NTHR, 3)
main_kernel(const float* __restrict__ x,
            const float* __restrict__ lnscale, const float* __restrict__ lnbias,
            const float* __restrict__ b1g, const float* __restrict__ b2g,
            float* __restrict__ out) {
    extern __shared__ char sm[];
    float* sT  = (float*)(sm + OFF_T);
    unsigned* sB1h = (unsigned*)(sm + OFF_B1);
    float* sB2 = (float*)(sm + OFF_B2);
    float* sLS = (float*)(sm + OFF_LS);
    float* sLB = (float*)(sm + OFF_LB);
    int*   sIdx = (int*)(sm + OFF_IDX);
    unsigned smem_base = (unsigned)__cvta_generic_to_shared(sm);

    int tid = threadIdx.x;
    int lane = tid & 31, w = tid >> 5;
    int tb = w * 32;                 // this warp's 32 tokens
    int b = blockIdx.y, n0 = blockIdx.x * TOKB;

    int r = lane >> 2;               // fragment row within 8
    int c2 = (lane & 3) * 2;         // fragment col pair
    int r15 = lane & 15;
    int colsel = ((lane >> 4) & 1) * 8;
    int row0a = tb + r,      row1a = row0a + 8;   // M-tile A
    int row0b = tb + 16 + r, row1b = row0b + 8;   // M-tile B

    // ---- stage chunk 0 weights (async, overlaps gathers) ----
    {
        const char* s1 = (const char*)g_w1;
        const char* s2 = (const char*)g_w2;
        unsigned dst = smem_base + OFF_W;
        for (int i = tid * 16; i < 64 * W1_S * 2; i += NTHR * 16) cp16(dst + i, s1 + i);
        for (int i = tid * 16; i < 128 * W2_S * 2; i += NTHR * 16) cp16(dst + 17408 + i, s2 + i);
        asm volatile("cp.async.commit_group;");
    }

    // ---- token index list, then gather x tile: sT[t][c] ----
    sIdx[tid] = g_idx[(size_t)b * KSEL + n0 + tid];
    for (int i = tid; i < HID; i += NTHR)
        sB1h[i] = pack_h2(make_float2(b1g[2 * i], b1g[2 * i + 1]));
    if (tid < 2 * CH) {
        sB2[tid] = b2g[tid];
        sLS[tid] = lnscale[tid];
        sLB[tid] = lnbias[tid];
    }
    __syncthreads();
    const float* xb = x + (size_t)b * CH * NPIX;
    {
        int t = tid;                   // NTHR == TOKB: one token per thread
        int gi = sIdx[t];
        #pragma unroll 8
        for (int c = 0; c < CH; ++c)
            sT[t * ST_S + c] = xb[(size_t)c * NPIX + gi];
    }
    __syncthreads();

    for (int layer = 0; layer < 2; ++layer) {
        // ---- LN stats: 1 lane per token (full 64-ch row) ----
        float mu, rs;
        {
            const float* rowp = sT + (tb + lane) * ST_S;
            float s = 0.f, s2 = 0.f;
            #pragma unroll
            for (int k = 0; k < 64; k += 4) {
                float4 v = *(const float4*)(rowp + k);
                s  += v.x + v.y + v.z + v.w;
                s2 += v.x * v.x + v.y * v.y + v.z * v.z + v.w * v.w;
            }
            mu = s * (1.f / 64.f);
            float var = s2 * (1.f / 64.f) - mu * mu;
            rs = rsqrtf(var + 1e-5f);
        }
        float mu0a = __shfl_sync(0xffffffffu, mu, r);
        float rs0a = __shfl_sync(0xffffffffu, rs, r);
        float mu1a = __shfl_sync(0xffffffffu, mu, r + 8);
        float rs1a = __shfl_sync(0xffffffffu, rs, r + 8);
        float mu0b = __shfl_sync(0xffffffffu, mu, r + 16);
        float rs0b = __shfl_sync(0xffffffffu, rs, r + 16);
        float mu1b = __shfl_sync(0xffffffffu, mu, r + 24);
        float rs1b = __shfl_sync(0xffffffffu, rs, r + 24);

        // ---- build GEMM1 A-fragments (Xn), fp16, two M-tiles ----
        unsigned aXa[16], aXb[16];
        #pragma unroll
        for (int kt = 0; kt < 4; ++kt) {
            int cA = kt * 16 + c2;
            float2 lsA = *(const float2*)(sLS + layer * 64 + cA);
            float2 lbA = *(const float2*)(sLB + layer * 64 + cA);
            float2 lsB = *(const float2*)(sLS + layer * 64 + cA + 8);
            float2 lbB = *(const float2*)(sLB + layer * 64 + cA + 8);
            float2 v;
            v = *(const float2*)(sT + row0a * ST_S + cA);
            v.x = (v.x - mu0a) * rs0a * lsA.x + lbA.x;
            v.y = (v.y - mu0a) * rs0a * lsA.y + lbA.y;
            aXa[kt * 4 + 0] = pack_h2(v);
            v = *(const float2*)(sT + row1a * ST_S + cA);
            v.x = (v.x - mu1a) * rs1a * lsA.x + lbA.x;
            v.y = (v.y - mu1a) * rs1a * lsA.y + lbA.y;
            aXa[kt * 4 + 1] = pack_h2(v);
            v = *(const float2*)(sT + row0a * ST_S + cA + 8);
            v.x = (v.x - mu0a) * rs0a * lsB.x + lbB.x;
            v.y = (v.y - mu0a) * rs0a * lsB.y + lbB.y;
            aXa[kt * 4 + 2] = pack_h2(v);
            v = *(const float2*)(sT + row1a * ST_S + cA + 8);
            v.x = (v.x - mu1a) * rs1a * lsB.x + lbB.x;
            v.y = (v.y - mu1a) * rs1a * lsB.y + lbB.y;
            aXa[kt * 4 + 3] = pack_h2(v);

            v = *(const float2*)(sT + row0b * ST_S + cA);
            v.x = (v.x - mu0b) * rs0b * lsA.x + lbA.x;
            v.y = (v.y - mu0b) * rs0b * lsA.y + lbA.y;
            aXb[kt * 4 + 0] = pack_h2(v);
            v = *(const float2*)(sT + row1b * ST_S + cA);
            v.x = (v.x - mu1b) * rs1b * lsA.x + lbA.x;
            v.y = (v.y - mu1b) * rs1b * lsA.y + lbA.y;
            aXb[kt * 4 + 1] = pack_h2(v);
            v = *(const float2*)(sT + row0b * ST_S + cA + 8);
            v.x = (v.x - mu0b) * rs0b * lsB.x + lbB.x;
            v.y = (v.y - mu0b) * rs0b * lsB.y + lbB.y;
            aXb[kt * 4 + 2] = pack_h2(v);
            v = *(const float2*)(sT + row1b * ST_S + cA + 8);
            v.x = (v.x - mu1b) * rs1b * lsB.x + lbB.x;
            v.y = (v.y - mu1b) * rs1b * lsB.y + lbB.y;
            aXb[kt * 4 + 3] = pack_h2(v);
        }

        float d2a[32], d2b[32];
        #pragma unroll
        for (int i = 0; i < 32; ++i) { d2a[i] = 0.f; d2b[i] = 0.f; }

        for (int jc = 0; jc < 2; ++jc) {
            int ch = layer * 2 + jc;
            unsigned wbase = smem_base + OFF_W;

            // ---- wait for this chunk's weights ----
            asm volatile("cp.async.wait_group 0;");
            __syncthreads();

            // ---- epilogue-lag pipeline: G1(jg) ; G2(a2 of jg-1) ; epi(jg)->a2 ----
            unsigned a2a[4], a2b[4];
            #pragma unroll
            for (int jg = 0; jg < 8; ++jg) {
                // GEMM1(jg): two 16x16 M-tiles, K=64, shared B frags
                float d1a[8], d1b[8];
                #pragma unroll
                for (int i = 0; i < 8; ++i) { d1a[i] = 0.f; d1b[i] = 0.f; }
                #pragma unroll
                for (int kt = 0; kt < 4; ++kt) {
                    unsigned bh[4];
                    unsigned boff = (unsigned)((kt * 16 + r15) * W1_S + jg * 16 + colsel) * 2;
                    ldsm_x4t(bh, wbase + boff);
                    mma_f16(d1a,     aXa + kt * 4, bh[0], bh[1]);
                    mma_f16(d1b,     aXb + kt * 4, bh[0], bh[1]);
                    mma_f16(d1a + 4, aXa + kt * 4, bh[2], bh[3]);
                    mma_f16(d1b + 4, aXb + kt * 4, bh[2], bh[3]);
                }
                // GEMM2(jg-1): uses a2 computed LAST iteration
                if (jg > 0) {
                    int jp = jg - 1;
                    #pragma unroll
                    for (int np = 0; np < 4; ++np) {
                        unsigned bh[4];
                        unsigned boff = (unsigned)((jp * 16 + r15) * W2_S + np * 16 + colsel) * 2;
                        ldsm_x4t(bh, wbase + 17408 + boff);
                        mma_f16(d2a + np * 8,     a2a, bh[0], bh[1]);
                        mma_f16(d2b + np * 8,     a2b, bh[0], bh[1]);
                        mma_f16(d2a + np * 8 + 4, a2a, bh[2], bh[3]);
                        mma_f16(d2b + np * 8 + 4, a2b, bh[2], bh[3]);
                    }
                }
                // epilogue(jg): pack + bias + gelu -> a2
                {
                    int j0 = jc * 128 + jg * 16;
                    int pb = (layer * HID + j0) >> 1;
                    unsigned b0 = sB1h[pb + (c2 >> 1)];
                    unsigned b8 = sB1h[pb + 4 + (c2 >> 1)];
                    __half2 b0h = *(__half2*)&b0, b8h = *(__half2*)&b8;
                    __half2 t; unsigned tu;
                    #define GEPI(dst, dd, bb) \
                        tu = pack_h2(make_float2((dd)[0], (dd)[1])); \
                        t = __hadd2(*(__half2*)&tu, bb); \
                        dst = gelu_h2(*(unsigned*)&t);
                    GEPI(a2a[0], d1a + 0, b0h); GEPI(a2a[1], d1a + 2, b0h);
                    GEPI(a2a[2], d1a + 4, b8h); GEPI(a2a[3], d1a + 6, b8h);
                    GEPI(a2b[0], d1b + 0, b0h); GEPI(a2b[1], d1b + 2, b0h);
                    GEPI(a2b[2], d1b + 4, b8h); GEPI(a2b[3], d1b + 6, b8h);
                    #undef GEPI
                }
            }
            // drain: GEMM2 for jg=7
            #pragma unroll
            for (int np = 0; np < 4; ++np) {
                unsigned bh[4];
                unsigned boff = (unsigned)((7 * 16 + r15) * W2_S + np * 16 + colsel) * 2;
                ldsm_x4t(bh, wbase + 17408 + boff);
                mma_f16(d2a + np * 8,     a2a, bh[0], bh[1]);
                mma_f16(d2b + np * 8,     a2b, bh[0], bh[1]);
                mma_f16(d2a + np * 8 + 4, a2a, bh[2], bh[3]);
                mma_f16(d2b + np * 8 + 4, a2b, bh[2], bh[3]);
            }
            __syncthreads();   // all warps done with buffer

            // ---- stage next chunk ----
            if (ch < 3) {
                int nc = ch + 1;
                const char* s1 = (const char*)(g_w1 + nc * 64 * W1_S);
                const char* s2 = (const char*)(g_w2 + nc * 128 * W2_S);
                unsigned dst = smem_base + OFF_W;
                for (int i = tid * 16; i < 64 * W1_S * 2; i += NTHR * 16) cp16(dst + i, s1 + i);
                for (int i = tid * 16; i < 128 * W2_S * 2; i += NTHR * 16) cp16(dst + 17408 + i, s2 + i);
                asm volatile("cp.async.commit_group;");
            }
        }

        // ---- unconditional residual add into sT (all tokens selected) ----
        {
            #pragma unroll
            for (int nt = 0; nt < 8; ++nt) {
                int c0 = nt * 8 + c2;
                float2 bv = *(const float2*)(sB2 + layer * 64 + c0);
                sT[row0a * ST_S + c0]     += d2a[nt * 4 + 0] + bv.x;
                sT[row0a * ST_S + c0 + 1] += d2a[nt * 4 + 1] + bv.y;
                sT[row1a * ST_S + c0]     += d2a[nt * 4 + 2] + bv.x;
                sT[row1a * ST_S + c0 + 1] += d2a[nt * 4 + 3] + bv.y;
                sT[row0b * ST_S + c0]     += d2b[nt * 4 + 0] + bv.x;
                sT[row0b * ST_S + c0 + 1] += d2b[nt * 4 + 1] + bv.y;
                sT[row1b * ST_S + c0]     += d2b[nt * 4 + 2] + bv.x;
                sT[row1b * ST_S + c0 + 1] += d2b[nt * 4 + 3] + bv.y;
            }
        }
        __syncwarp();
    }

    // ---- scatter store ----
    __syncthreads();
    float* ob = out + (size_t)b * CH * NPIX;
    {
        int t = tid;
        int gi = sIdx[t];
        #pragma unroll 8
        for (int c = 0; c < CH; ++c)
            ob[(size_t)c * NPIX + gi] = sT[t * ST_S + c];
    }
}

// ---------------- launch ----------------
extern "C" void kernel_launch(void* const* d_in, const int* in_sizes, int n_in,
                              void* d_out, int out_size) {
    const float* x    = (const float*)d_in[0];
    const float* prop = (const float*)d_in[1];
    const float* lns  = (const float*)d_in[2];
    const float* lnb  = (const float*)d_in[3];
    const float* w1   = (const float*)d_in[4];
    const float* b1   = (const float*)d_in[5];
    const float* w2   = (const float*)d_in[6];
    const float* b2   = (const float*)d_in[7];
    float* out = (float*)d_out;

    cudaFuncSetAttribute(main_kernel, cudaFuncAttributeMaxDynamicSharedMemorySize, SMEM_BYTES);
    int sel_smem = (NPIX + 260) * 4;
    cudaFuncSetAttribute(select_flags_kernel, cudaFuncAttributeMaxDynamicSharedMemorySize, sel_smem);

    select_flags_kernel<<<BATCH + 2, 1024, sel_smem>>>(prop, w1, w2);
    dim3 cgrid(NPIX / 128, BATCH);
    copy_kernel<<<cgrid, 128>>>(x, out);
    dim3 grid(KSEL / TOKB, BATCH);
    main_kernel<<<grid, NTHR, SMEM_BYTES>>>(x, lns, lnb, b1, b2, out);
}

// round 15
// speedup vs baseline: 2.5420x; 1.2551x over previous
#include <cuda_runtime.h>
#include <cuda_fp16.h>
#include <math.h>

#define BATCH 16
#define CH    64
#define NPIX  25600          // 160*160
#define HID   256
#define KSEL  20480          // ceil(25600*0.8); divisible by 128
#define TOKB  128            // tokens per block
#define NTHR  128            // 4 warps x 32 tokens each
#define MAINBLK (KSEL / TOKB)   // 160
#define COPYTOK 512
#define COPYBLK (NPIX / COPYTOK) // 50

#define ST_S  68             // sT fp32 row stride (272B)
#define W1_S  136            // fp16 elements per row (272B), chunk rows=64
#define W2_S  72             // fp16 elements per row (144B), chunk rows=128

// smem byte offsets (main kernel) -- SINGLE weight buffer, occupancy 3
#define OFF_T    0            // 128*68*4  = 34816
#define OFF_W    34816        // one chunk buffer 35840 (W1 17408 + W2 18432)
#define OFF_B1   70656        // 256 u32 (h2-packed bias1)
#define OFF_B2   71680        // 2*64*4 = 512
#define OFF_LS   72192        // 512
#define OFF_LB   72704        // 512
#define OFF_IDX  73216        // 128*4 = 512 (gathered token indices)
#define SMEM_BYTES 73728      // x3 CTAs = 221184 <= 227KB

// ---------------- static scratch ----------------
__device__ unsigned      g_thresh[BATCH];
__device__ int           g_ties[BATCH];
__device__ int           g_cnt[BATCH];
__device__ int           g_eqcnt[BATCH];
__device__ int           g_eqidx[BATCH * 1024];
__device__ unsigned char g_flags[BATCH * NPIX];
__device__ int           g_idx[BATCH * KSEL];
// pre-converted fp16 weights in smem tile layout (chunk = layer*2 + jc)
__device__ __align__(16) unsigned short g_w1[4 * 64 * W1_S];
__device__ __align__(16) unsigned short g_w2[4 * 128 * W2_S];

__device__ __forceinline__ unsigned fkey(float f) {
    unsigned u = __float_as_uint(f);
    return (u & 0x80000000u) ? ~u : (u | 0x80000000u);
}

__device__ __forceinline__ unsigned pack_h2(float2 v) {
    __half2 h = __float22half2_rn(v);
    return *(unsigned*)&h;
}

// gelu on a packed half2 (tanh approximation, all-fp16 math)
__device__ __forceinline__ unsigned gelu_h2(unsigned vu) {
    __half2 v = *(__half2*)&vu;
    const __half2 k0  = __floats2half2_rn(0.7978845608f, 0.7978845608f);
    const __half2 k01 = __floats2half2_rn(0.0356774081f, 0.0356774081f);  // k0*0.044715
    const __half2 hf  = __floats2half2_rn(0.5f, 0.5f);
    __half2 u = __hmul2(v, v);
    __half2 w = __hmul2(u, v);
    __half2 inner = __hfma2(w, k01, __hmul2(v, k0));
    unsigned tin = *(unsigned*)&inner, tout;
    asm("tanh.approx.f16x2 %0, %1;" : "=r"(tout) : "r"(tin));
    __half2 t = *(__half2*)&tout;
    __half2 hv = __hmul2(v, hf);
    __half2 res = __hfma2(hv, t, hv);
    return *(unsigned*)&res;
}

__device__ __forceinline__ void ldsm_x4t(unsigned* r, unsigned addr) {
    asm volatile("ldmatrix.sync.aligned.m8n8.x4.trans.shared.b16 {%0,%1,%2,%3}, [%4];"
                 : "=r"(r[0]), "=r"(r[1]), "=r"(r[2]), "=r"(r[3]) : "r"(addr));
}
__device__ __forceinline__ void mma_f16(float* d, const unsigned* a, unsigned b0, unsigned b1) {
    asm volatile("mma.sync.aligned.m16n8k16.row.col.f32.f16.f16.f32 "
                 "{%0,%1,%2,%3}, {%4,%5,%6,%7}, {%8,%9}, {%0,%1,%2,%3};"
                 : "+f"(d[0]), "+f"(d[1]), "+f"(d[2]), "+f"(d[3])
                 : "r"(a[0]), "r"(a[1]), "r"(a[2]), "r"(a[3]), "r"(b0), "r"(b1));
}
__device__ __forceinline__ void cp16(unsigned dst, const void* src) {
    asm volatile("cp.async.cg.shared.global [%0], [%1], 16;" :: "r"(dst), "l"(src));
}

// ---------------- kernel 1: fused prep + per-batch radix threshold ----------------
__global__ void select_kernel(const float* __restrict__ prop,
                              const float* __restrict__ w1g, const float* __restrict__ w2g) {
    int tid = threadIdx.x;
    if (blockIdx.x >= BATCH) {
        // ---- prep: pre-convert weights to fp16 smem-tile layout ----
        int base = (blockIdx.x - BATCH) * 16384;
        #pragma unroll 4
        for (int q = 0; q < 16; ++q) {
            int idx = base + q * 1024 + tid;
            int layer = idx >> 14;
            int rem = idx & 16383;
            {   // w1: [layer][c][j]
                int c = rem >> 8, j = rem & 255;
                __half h = __float2half_rn(w1g[idx]);
                int off = (layer * 2 + (j >> 7)) * 64 * W1_S + c * W1_S + (j & 127);
                g_w1[off] = *(unsigned short*)&h;
            }
            {   // w2: [layer][j][c]
                int j = rem >> 6, c = rem & 63;
                __half h = __float2half_rn(w2g[idx]);
                int off = (layer * 2 + (j >> 7)) * 128 * W2_S + (j & 127) * W2_S + c;
                g_w2[off] = *(unsigned short*)&h;
            }
        }
        return;
    }
    int b = blockIdx.x;
    const float* p = prop + (size_t)b * NPIX;
    extern __shared__ unsigned dyn[];
    unsigned* skey = dyn;              // 25600 keys
    unsigned* hist = dyn + NPIX;       // 256
    __shared__ unsigned s_prefix;
    __shared__ int s_k;
    __shared__ unsigned wtot[8];
    if (tid == 0) { s_prefix = 0u; s_k = KSEL; g_cnt[b] = 0; g_eqcnt[b] = 0; }
    for (int i = tid; i < NPIX; i += 1024) skey[i] = fkey(p[i]);
    __syncthreads();

    for (int pass = 3; pass >= 0; --pass) {
        int shift = pass * 8;
        if (tid < 256) hist[tid] = 0u;
        __syncthreads();
        unsigned prefix = s_prefix;
        unsigned highmask = (pass == 3) ? 0u : (0xFFFFFFFFu << (shift + 8));
        for (int i = tid; i < NPIX; i += 1024) {
            unsigned u = skey[i];
            if ((u & highmask) == prefix)
                atomicAdd(&hist[(u >> shift) & 255u], 1u);
        }
        __syncthreads();
        // ---- parallel suffix-sum digit selection (256 threads) ----
        int k = s_k;
        unsigned v = 0, h0 = 0;
        int l = tid & 31, w8 = tid >> 5;
        if (tid < 256) {
            v = hist[tid];
            h0 = v;
            #pragma unroll
            for (int off = 1; off < 32; off <<= 1) {
                unsigned t = __shfl_down_sync(0xffffffffu, v, off);
                if (l + off < 32) v += t;
            }
            if (l == 0) wtot[w8] = v;
        }
        __syncthreads();
        if (tid < 256) {
            unsigned suf = v;
            for (int q = w8 + 1; q < 8; ++q) suf += wtot[q];
            if ((int)suf >= k && (int)(suf - h0) < k) {
                s_prefix = prefix | ((unsigned)tid << shift);
                s_k = k - (int)(suf - h0);
            }
        }
        __syncthreads();
    }
    if (tid == 0) {
        g_thresh[b] = s_prefix;
        g_ties[b]   = s_k;
    }
}

// ---------------- kernel 2a: grid-parallel flags + block-sorted compaction ----------
__global__ void flags1_kernel(const float* __restrict__ prop) {
    int b = blockIdx.y;
    int tid = threadIdx.x;
    int i = blockIdx.x * 1024 + tid;
    int lane = tid & 31, w = tid >> 5;
    __shared__ int wsum[32];
    __shared__ int blockbase;
    unsigned T = g_thresh[b];
    unsigned u = fkey(prop[(size_t)b * NPIX + i]);
    int gt = (u > T), eq = (u == T);
    g_flags[(size_t)b * NPIX + i] = (unsigned char)gt;   // eq selections patched by flags2
    // block-local exclusive scan of gt (keeps g_idx piecewise ascending for coalesced gathers)
    unsigned ball = __ballot_sync(0xffffffffu, gt);
    int pre = __popc(ball & ((1u << lane) - 1u));
    if (lane == 0) wsum[w] = __popc(ball);
    __syncthreads();
    if (tid == 0) {
        int acc = 0;
        for (int q = 0; q < 32; ++q) { int t = wsum[q]; wsum[q] = acc; acc += t; }
        blockbase = atomicAdd(&g_cnt[b], acc);
    }
    __syncthreads();
    if (gt) g_idx[(size_t)b * KSEL + blockbase + wsum[w] + pre] = i;
    // eq capture (rare): plain warp-aggregated atomic
    unsigned balle = __ballot_sync(0xffffffffu, eq);
    if (balle) {
        int leader = __ffs(balle) - 1;
        int cnt = __popc(balle);
        int pree = __popc(balle & ((1u << lane) - 1u));
        int basee = 0;
        if (lane == leader) basee = atomicAdd(&g_eqcnt[b], cnt);
        basee = __shfl_sync(0xffffffffu, basee, leader);
        if (eq) g_eqidx[b * 1024 + basee + pree] = i;
    }
}

// ---------------- kernel 2b: tie fixup (n expected ~1) ----------------
__global__ void flags2_kernel() {
    int b = blockIdx.x;
    int n = g_eqcnt[b];
    int ties = g_ties[b];
    for (int e = threadIdx.x; e < n; e += 256) {
        int idx = g_eqidx[b * 1024 + e];
        int rank = 0;
        for (int q = 0; q < n; ++q)
            rank += (g_eqidx[b * 1024 + q] < idx) ? 1 : 0;
        if (rank < ties) {
            g_flags[(size_t)b * NPIX + idx] = 1;
            int pos = atomicAdd(&g_cnt[b], 1);
            g_idx[(size_t)b * KSEL + pos] = idx;
        }
    }
}

// ---------------- kernel 3: fused LN + MLP over compacted tokens + merged copy ----------
__global__ void __launch_bounds__(NTHR, 3)
main_kernel(const float* __restrict__ x,
            const float* __restrict__ lnscale, const float* __restrict__ lnbias,
            const float* __restrict__ b1g, const float* __restrict__ b2g,
            float* __restrict__ out) {
    int tid = threadIdx.x;
    int b = blockIdx.y;

    // ---- merged pass-through copy path (overlaps MLP blocks) ----
    if (blockIdx.x >= MAINBLK) {
        int t0 = (blockIdx.x - MAINBLK) * COPYTOK + tid;
        const float* xb = x + (size_t)b * CH * NPIX;
        float* ob = out + (size_t)b * CH * NPIX;
        #pragma unroll
        for (int k = 0; k < COPYTOK / NTHR; ++k) {
            int i = t0 + k * NTHR;
            if (g_flags[(size_t)b * NPIX + i]) continue;
            #pragma unroll 8
            for (int c = 0; c < CH; ++c)
                ob[(size_t)c * NPIX + i] = xb[(size_t)c * NPIX + i];
        }
        return;
    }

    extern __shared__ char sm[];
    float* sT  = (float*)(sm + OFF_T);
    unsigned* sB1h = (unsigned*)(sm + OFF_B1);
    float* sB2 = (float*)(sm + OFF_B2);
    float* sLS = (float*)(sm + OFF_LS);
    float* sLB = (float*)(sm + OFF_LB);
    int*   sIdx = (int*)(sm + OFF_IDX);
    unsigned smem_base = (unsigned)__cvta_generic_to_shared(sm);

    int lane = tid & 31, w = tid >> 5;
    int tb = w * 32;                 // this warp's 32 tokens
    int n0 = blockIdx.x * TOKB;

    int r = lane >> 2;               // fragment row within 8
    int c2 = (lane & 3) * 2;         // fragment col pair
    int r15 = lane & 15;
    int colsel = ((lane >> 4) & 1) * 8;
    int row0a = tb + r,      row1a = row0a + 8;   // M-tile A
    int row0b = tb + 16 + r, row1b = row0b + 8;   // M-tile B

    // ---- stage chunk 0 weights (async, overlaps gathers) ----
    {
        const char* s1 = (const char*)g_w1;
        const char* s2 = (const char*)g_w2;
        unsigned dst = smem_base + OFF_W;
        for (int i = tid * 16; i < 64 * W1_S * 2; i += NTHR * 16) cp16(dst + i, s1 + i);
        for (int i = tid * 16; i < 128 * W2_S * 2; i += NTHR * 16) cp16(dst + 17408 + i, s2 + i);
        asm volatile("cp.async.commit_group;");
    }

    // ---- token index list, then gather x tile: sT[t][c] ----
    sIdx[tid] = g_idx[(size_t)b * KSEL + n0 + tid];
    for (int i = tid; i < HID; i += NTHR)
        sB1h[i] = pack_h2(make_float2(b1g[2 * i], b1g[2 * i + 1]));
    if (tid < 2 * CH) {
        sB2[tid] = b2g[tid];
        sLS[tid] = lnscale[tid];
        sLB[tid] = lnbias[tid];
    }
    __syncthreads();
    const float* xb = x + (size_t)b * CH * NPIX;
    {
        int t = tid;                   // NTHR == TOKB: one token per thread
        int gi = sIdx[t];
        #pragma unroll 8
        for (int c = 0; c < CH; ++c)
            sT[t * ST_S + c] = xb[(size_t)c * NPIX + gi];
    }
    __syncthreads();

    for (int layer = 0; layer < 2; ++layer) {
        // ---- LN stats: 1 lane per token (full 64-ch row) ----
        float mu, rs;
        {
            const float* rowp = sT + (tb + lane) * ST_S;
            float s = 0.f, s2 = 0.f;
            #pragma unroll
            for (int k = 0; k < 64; k += 4) {
                float4 v = *(const float4*)(rowp + k);
                s  += v.x + v.y + v.z + v.w;
                s2 += v.x * v.x + v.y * v.y + v.z * v.z + v.w * v.w;
            }
            mu = s * (1.f / 64.f);
            float var = s2 * (1.f / 64.f) - mu * mu;
            rs = rsqrtf(var + 1e-5f);
        }
        float mu0a = __shfl_sync(0xffffffffu, mu, r);
        float rs0a = __shfl_sync(0xffffffffu, rs, r);
        float mu1a = __shfl_sync(0xffffffffu, mu, r + 8);
        float rs1a = __shfl_sync(0xffffffffu, rs, r + 8);
        float mu0b = __shfl_sync(0xffffffffu, mu, r + 16);
        float rs0b = __shfl_sync(0xffffffffu, rs, r + 16);
        float mu1b = __shfl_sync(0xffffffffu, mu, r + 24);
        float rs1b = __shfl_sync(0xffffffffu, rs, r + 24);

        // ---- build GEMM1 A-fragments (Xn), fp16, two M-tiles ----
        unsigned aXa[16], aXb[16];
        #pragma unroll
        for (int kt = 0; kt < 4; ++kt) {
            int cA = kt * 16 + c2;
            float2 lsA = *(const float2*)(sLS + layer * 64 + cA);
            float2 lbA = *(const float2*)(sLB + layer * 64 + cA);
            float2 lsB = *(const float2*)(sLS + layer * 64 + cA + 8);
            float2 lbB = *(const float2*)(sLB + layer * 64 + cA + 8);
            float2 v;
            v = *(const float2*)(sT + row0a * ST_S + cA);
            v.x = (v.x - mu0a) * rs0a * lsA.x + lbA.x;
            v.y = (v.y - mu0a) * rs0a * lsA.y + lbA.y;
            aXa[kt * 4 + 0] = pack_h2(v);
            v = *(const float2*)(sT + row1a * ST_S + cA);
            v.x = (v.x - mu1a) * rs1a * lsA.x + lbA.x;
            v.y = (v.y - mu1a) * rs1a * lsA.y + lbA.y;
            aXa[kt * 4 + 1] = pack_h2(v);
            v = *(const float2*)(sT + row0a * ST_S + cA + 8);
            v.x = (v.x - mu0a) * rs0a * lsB.x + lbB.x;
            v.y = (v.y - mu0a) * rs0a * lsB.y + lbB.y;
            aXa[kt * 4 + 2] = pack_h2(v);
            v = *(const float2*)(sT + row1a * ST_S + cA + 8);
            v.x = (v.x - mu1a) * rs1a * lsB.x + lbB.x;
            v.y = (v.y - mu1a) * rs1a * lsB.y + lbB.y;
            aXa[kt * 4 + 3] = pack_h2(v);

            v = *(const float2*)(sT + row0b * ST_S + cA);
            v.x = (v.x - mu0b) * rs0b * lsA.x + lbA.x;
            v.y = (v.y - mu0b) * rs0b * lsA.y + lbA.y;
            aXb[kt * 4 + 0] = pack_h2(v);
            v = *(const float2*)(sT + row1b * ST_S + cA);
            v.x = (v.x - mu1b) * rs1b * lsA.x + lbA.x;
            v.y = (v.y - mu1b) * rs1b * lsA.y + lbA.y;
            aXb[kt * 4 + 1] = pack_h2(v);
            v = *(const float2*)(sT + row0b * ST_S + cA + 8);
            v.x = (v.x - mu0b) * rs0b * lsB.x + lbB.x;
            v.y = (v.y - mu0b) * rs0b * lsB.y + lbB.y;
            aXb[kt * 4 + 2] = pack_h2(v);
            v = *(const float2*)(sT + row1b * ST_S + cA + 8);
            v.x = (v.x - mu1b) * rs1b * lsB.x + lbB.x;
            v.y = (v.y - mu1b) * rs1b * lsB.y + lbB.y;
            aXb[kt * 4 + 3] = pack_h2(v);
        }

        float d2a[32], d2b[32];
        #pragma unroll
        for (int i = 0; i < 32; ++i) { d2a[i] = 0.f; d2b[i] = 0.f; }

        for (int jc = 0; jc < 2; ++jc) {
            int ch = layer * 2 + jc;
            unsigned wbase = smem_base + OFF_W;

            // ---- wait for this chunk's weights ----
            asm volatile("cp.async.wait_group 0;");
            __syncthreads();

            // ---- epilogue-lag pipeline: G1(jg) ; G2(a2 of jg-1) ; epi(jg)->a2 ----
            unsigned a2a[4], a2b[4];
            #pragma unroll
            for (int jg = 0; jg < 8; ++jg) {
                // GEMM1(jg): two 16x16 M-tiles, K=64, shared B frags
                float d1a[8], d1b[8];
                #pragma unroll
                for (int i = 0; i < 8; ++i) { d1a[i] = 0.f; d1b[i] = 0.f; }
                #pragma unroll
                for (int kt = 0; kt < 4; ++kt) {
                    unsigned bh[4];
                    unsigned boff = (unsigned)((kt * 16 + r15) * W1_S + jg * 16 + colsel) * 2;
                    ldsm_x4t(bh, wbase + boff);
                    mma_f16(d1a,     aXa + kt * 4, bh[0], bh[1]);
                    mma_f16(d1b,     aXb + kt * 4, bh[0], bh[1]);
                    mma_f16(d1a + 4, aXa + kt * 4, bh[2], bh[3]);
                    mma_f16(d1b + 4, aXb + kt * 4, bh[2], bh[3]);
                }
                // GEMM2(jg-1): uses a2 computed LAST iteration
                if (jg > 0) {
                    int jp = jg - 1;
                    #pragma unroll
                    for (int np = 0; np < 4; ++np) {
                        unsigned bh[4];
                        unsigned boff = (unsigned)((jp * 16 + r15) * W2_S + np * 16 + colsel) * 2;
                        ldsm_x4t(bh, wbase + 17408 + boff);
                        mma_f16(d2a + np * 8,     a2a, bh[0], bh[1]);
                        mma_f16(d2b + np * 8,     a2b, bh[0], bh[1]);
                        mma_f16(d2a + np * 8 + 4, a2a, bh[2], bh[3]);
                        mma_f16(d2b + np * 8 + 4, a2b, bh[2], bh[3]);
                    }
                }
                // epilogue(jg): pack + bias + gelu -> a2
                {
                    int j0 = jc * 128 + jg * 16;
                    int pb = (layer * HID + j0) >> 1;
                    unsigned b0 = sB1h[pb + (c2 >> 1)];
                    unsigned b8 = sB1h[pb + 4 + (c2 >> 1)];
                    __half2 b0h = *(__half2*)&b0, b8h = *(__half2*)&b8;
                    __half2 t; unsigned tu;
                    #define GEPI(dst, dd, bb) \
                        tu = pack_h2(make_float2((dd)[0], (dd)[1])); \
                        t = __hadd2(*(__half2*)&tu, bb); \
                        dst = gelu_h2(*(unsigned*)&t);
                    GEPI(a2a[0], d1a + 0, b0h); GEPI(a2a[1], d1a + 2, b0h);
                    GEPI(a2a[2], d1a + 4, b8h); GEPI(a2a[3], d1a + 6, b8h);
                    GEPI(a2b[0], d1b + 0, b0h); GEPI(a2b[1], d1b + 2, b0h);
                    GEPI(a2b[2], d1b + 4, b8h); GEPI(a2b[3], d1b + 6, b8h);
                    #undef GEPI
                }
            }
            // drain: GEMM2 for jg=7
            #pragma unroll
            for (int np = 0; np < 4; ++np) {
                unsigned bh[4];
                unsigned boff = (unsigned)((7 * 16 + r15) * W2_S + np * 16 + colsel) * 2;
                ldsm_x4t(bh, wbase + 17408 + boff);
                mma_f16(d2a + np * 8,     a2a, bh[0], bh[1]);
                mma_f16(d2b + np * 8,     a2b, bh[0], bh[1]);
                mma_f16(d2a + np * 8 + 4, a2a, bh[2], bh[3]);
                mma_f16(d2b + np * 8 + 4, a2b, bh[2], bh[3]);
            }
            __syncthreads();   // all warps done with buffer

            // ---- stage next chunk ----
            if (ch < 3) {
                int nc = ch + 1;
                const char* s1 = (const char*)(g_w1 + nc * 64 * W1_S);
                const char* s2 = (const char*)(g_w2 + nc * 128 * W2_S);
                unsigned dst = smem_base + OFF_W;
                for (int i = tid * 16; i < 64 * W1_S * 2; i += NTHR * 16) cp16(dst + i, s1 + i);
                for (int i = tid * 16; i < 128 * W2_S * 2; i += NTHR * 16) cp16(dst + 17408 + i, s2 + i);
                asm volatile("cp.async.commit_group;");
            }
        }

        // ---- unconditional residual add into sT (all tokens selected) ----
        {
            #pragma unroll
            for (int nt = 0; nt < 8; ++nt) {
                int c0 = nt * 8 + c2;
                float2 bv = *(const float2*)(sB2 + layer * 64 + c0);
                sT[row0a * ST_S + c0]     += d2a[nt * 4 + 0] + bv.x;
                sT[row0a * ST_S + c0 + 1] += d2a[nt * 4 + 1] + bv.y;
                sT[row1a * ST_S + c0]     += d2a[nt * 4 + 2] + bv.x;
                sT[row1a * ST_S + c0 + 1] += d2a[nt * 4 + 3] + bv.y;
                sT[row0b * ST_S + c0]     += d2b[nt * 4 + 0] + bv.x;
                sT[row0b * ST_S + c0 + 1] += d2b[nt * 4 + 1] + bv.y;
                sT[row1b * ST_S + c0]     += d2b[nt * 4 + 2] + bv.x;
                sT[row1b * ST_S + c0 + 1] += d2b[nt * 4 + 3] + bv.y;
            }
        }
        __syncwarp();
    }

    // ---- scatter store ----
    __syncthreads();
    float* ob = out + (size_t)b * CH * NPIX;
    {
        int t = tid;
        int gi = sIdx[t];
        #pragma unroll 8
        for (int c = 0; c < CH; ++c)
            ob[(size_t)c * NPIX + gi] = sT[t * ST_S + c];
    }
}

// ---------------- launch ----------------
extern "C" void kernel_launch(void* const* d_in, const int* in_sizes, int n_in,
                              void* d_out, int out_size) {
    const float* x    = (const float*)d_in[0];
    const float* prop = (const float*)d_in[1];
    const float* lns  = (const float*)d_in[2];
    const float* lnb  = (const float*)d_in[3];
    const float* w1   = (const float*)d_in[4];
    const float* b1   = (const float*)d_in[5];
    const float* w2   = (const float*)d_in[6];
    const float* b2   = (const float*)d_in[7];
    float* out = (float*)d_out;

    cudaFuncSetAttribute(main_kernel, cudaFuncAttributeMaxDynamicSharedMemorySize, SMEM_BYTES);
    int sel_smem = (NPIX + 260) * 4;
    cudaFuncSetAttribute(select_kernel, cudaFuncAttributeMaxDynamicSharedMemorySize, sel_smem);

    select_kernel<<<BATCH + 2, 1024, sel_smem>>>(prop, w1, w2);
    dim3 fgrid(NPIX / 1024, BATCH);
    flags1_kernel<<<fgrid, 1024>>>(prop);
    flags2_kernel<<<BATCH, 256>>>();
    dim3 grid(MAINBLK + COPYBLK, BATCH);
    main_kernel<<<grid, NTHR, SMEM_BYTES>>>(x, lns, lnb, b1, b2, out);
}

// round 16
// speedup vs baseline: 2.5677x; 1.0101x over previous
#include <cuda_runtime.h>
#include <cuda_fp16.h>
#include <math.h>

#define BATCH 16
#define CH    64
#define NPIX  25600          // 160*160
#define HID   256
#define KSEL  20480          // ceil(25600*0.8); divisible by 128
#define TOKB  128            // tokens per block
#define NTHR  128            // 4 warps x 32 tokens each
#define MAINBLK (KSEL / TOKB)   // 160
#define COPYTOK 512
#define COPYBLK (NPIX / COPYTOK) // 50
#define CAP   12288          // candidate cap for select compaction

#define ST_S  68             // sT fp32 row stride (272B)
#define WH_S  72             // half-chunk row stride, fp16 elems (144B)
#define HC_ELEMS 9216        // elems per half-chunk (W1half 64*72 + W2half 64*72)
#define HC_BYTES 18432
#define W2REG 9216           // byte offset of W2half within a half-chunk

// smem byte offsets (main kernel) -- TWO half-chunk buffers, occupancy 3
#define OFF_T    0            // 128*68*4  = 34816
#define OFF_W    34816        // 2 x 18432 = 36864
#define OFF_B1   71680        // 256 u32 (h2-packed bias1)
#define OFF_B2   72704        // 512
#define OFF_LS   73216        // 512
#define OFF_LB   73728        // 512
#define OFF_IDX  74240        // 512
#define SMEM_BYTES 74752      // x3 CTAs = 224256 <= 227KB

// ---------------- static scratch ----------------
__device__ unsigned      g_thresh[BATCH];
__device__ int           g_ties[BATCH];
__device__ int           g_cnt[BATCH];
__device__ int           g_eqcnt[BATCH];
__device__ int           g_eqidx[BATCH * 1024];
__device__ unsigned char g_flags[BATCH * NPIX];
__device__ int           g_idx[BATCH * KSEL];
// pre-converted fp16 weights, half-chunk layout: hc = layer*4 + (j>>6)
__device__ __align__(16) unsigned short g_whc[8 * HC_ELEMS];

__device__ __forceinline__ unsigned fkey(float f) {
    unsigned u = __float_as_uint(f);
    return (u & 0x80000000u) ? ~u : (u | 0x80000000u);
}

__device__ __forceinline__ unsigned pack_h2(float2 v) {
    __half2 h = __float22half2_rn(v);
    return *(unsigned*)&h;
}

// gelu on a packed half2 (tanh approximation, all-fp16 math)
__device__ __forceinline__ unsigned gelu_h2(unsigned vu) {
    __half2 v = *(__half2*)&vu;
    const __half2 k0  = __floats2half2_rn(0.7978845608f, 0.7978845608f);
    const __half2 k01 = __floats2half2_rn(0.0356774081f, 0.0356774081f);  // k0*0.044715
    const __half2 hf  = __floats2half2_rn(0.5f, 0.5f);
    __half2 u = __hmul2(v, v);
    __half2 w = __hmul2(u, v);
    __half2 inner = __hfma2(w, k01, __hmul2(v, k0));
    unsigned tin = *(unsigned*)&inner, tout;
    asm("tanh.approx.f16x2 %0, %1;" : "=r"(tout) : "r"(tin));
    __half2 t = *(__half2*)&tout;
    __half2 hv = __hmul2(v, hf);
    __half2 res = __hfma2(hv, t, hv);
    return *(unsigned*)&res;
}

__device__ __forceinline__ void ldsm_x4t(unsigned* r, unsigned addr) {
    asm volatile("ldmatrix.sync.aligned.m8n8.x4.trans.shared.b16 {%0,%1,%2,%3}, [%4];"
                 : "=r"(r[0]), "=r"(r[1]), "=r"(r[2]), "=r"(r[3]) : "r"(addr));
}
__device__ __forceinline__ void mma_f16(float* d, const unsigned* a, unsigned b0, unsigned b1) {
    asm volatile("mma.sync.aligned.m16n8k16.row.col.f32.f16.f16.f32 "
                 "{%0,%1,%2,%3}, {%4,%5,%6,%7}, {%8,%9}, {%0,%1,%2,%3};"
                 : "+f"(d[0]), "+f"(d[1]), "+f"(d[2]), "+f"(d[3])
                 : "r"(a[0]), "r"(a[1]), "r"(a[2]), "r"(a[3]), "r"(b0), "r"(b1));
}
__device__ __forceinline__ void cp16(unsigned dst, const void* src) {
    asm volatile("cp.async.cg.shared.global [%0], [%1], 16;" :: "r"(dst), "l"(src));
}

// ---------------- kernel 1: fused prep + per-batch radix threshold ----------------
__global__ void select_kernel(const float* __restrict__ prop,
                              const float* __restrict__ w1g, const float* __restrict__ w2g) {
    int tid = threadIdx.x;
    if (blockIdx.x >= BATCH) {
        // ---- prep: pre-convert weights to fp16 half-chunk layout ----
        int base = (blockIdx.x - BATCH) * 16384;
        #pragma unroll 4
        for (int q = 0; q < 16; ++q) {
            int idx = base + q * 1024 + tid;
            int layer = idx >> 14;
            int rem = idx & 16383;
            {   // w1: [layer][c][j] -> hc = layer*4 + (j>>6), elem c*WH_S + (j&63)
                int c = rem >> 8, j = rem & 255;
                __half h = __float2half_rn(w1g[idx]);
                g_whc[(layer * 4 + (j >> 6)) * HC_ELEMS + c * WH_S + (j & 63)] = *(unsigned short*)&h;
            }
            {   // w2: [layer][j][c] -> hc = layer*4 + (j>>6), elem 4608 + (j&63)*WH_S + c
                int j = rem >> 6, c = rem & 63;
                __half h = __float2half_rn(w2g[idx]);
                g_whc[(layer * 4 + (j >> 6)) * HC_ELEMS + 4608 + (j & 63) * WH_S + c] = *(unsigned short*)&h;
            }
        }
        return;
    }
    int b = blockIdx.x;
    const float* p = prop + (size_t)b * NPIX;
    extern __shared__ unsigned dyn[];
    unsigned* skey = dyn;                  // NPIX
    unsigned* hist = dyn + NPIX;           // 256
    unsigned* cand = dyn + NPIX + 256;     // CAP
    __shared__ unsigned s_prefix;
    __shared__ int s_k;
    __shared__ int s_n;
    __shared__ unsigned wtot[8];
    int lane = tid & 31, w8 = tid >> 5;
    if (tid == 0) { s_prefix = 0u; s_k = KSEL; s_n = 0; g_cnt[b] = 0; g_eqcnt[b] = 0; }
    if (tid < 256) hist[tid] = 0u;
    __syncthreads();
    // ---- load keys + top-byte histogram in one sweep ----
    for (int i = tid; i < NPIX; i += 1024) {
        unsigned u = fkey(p[i]);
        skey[i] = u;
        atomicAdd(&hist[u >> 24], 1u);
    }
    __syncthreads();
    // ---- digit select for shift=24 ----
    {
        int k = s_k;
        unsigned v = 0, h0 = 0;
        if (tid < 256) {
            v = hist[tid]; h0 = v;
            #pragma unroll
            for (int off = 1; off < 32; off <<= 1) {
                unsigned t = __shfl_down_sync(0xffffffffu, v, off);
                if (lane + off < 32) v += t;
            }
            if (lane == 0) wtot[w8] = v;
        }
        __syncthreads();
        if (tid < 256) {
            unsigned suf = v;
            for (int q = w8 + 1; q < 8; ++q) suf += wtot[q];
            if ((int)suf >= k && (int)(suf - h0) < k) {
                s_prefix = (unsigned)tid << 24;
                s_k = k - (int)(suf - h0);
            }
        }
        __syncthreads();
    }
    // ---- compact candidates matching top byte ----
    {
        unsigned pref8 = s_prefix;
        for (int i = tid; i < NPIX; i += 1024) {
            unsigned u = skey[i];
            if ((u & 0xFF000000u) == pref8) {
                int pos = atomicAdd(&s_n, 1);
                if (pos < CAP) cand[pos] = u;
            }
        }
    }
    __syncthreads();
    int ncand = s_n;
    bool ok = (ncand <= CAP);
    if (!ok) ncand = NPIX;          // fallback: scan full skey

    for (int pass = 2; pass >= 0; --pass) {
        int shift = pass * 8;
        if (tid < 256) hist[tid] = 0u;
        __syncthreads();
        unsigned prefix = s_prefix;
        unsigned highmask = 0xFFFFFFFFu << (shift + 8);
        const unsigned* src = ok ? cand : skey;
        for (int i = tid; i < ncand; i += 1024) {
            unsigned u = src[i];
            if ((u & highmask) == prefix)
                atomicAdd(&hist[(u >> shift) & 255u], 1u);
        }
        __syncthreads();
        int k = s_k;
        unsigned v = 0, h0 = 0;
        if (tid < 256) {
            v = hist[tid]; h0 = v;
            #pragma unroll
            for (int off = 1; off < 32; off <<= 1) {
                unsigned t = __shfl_down_sync(0xffffffffu, v, off);
                if (lane + off < 32) v += t;
            }
            if (lane == 0) wtot[w8] = v;
        }
        __syncthreads();
        if (tid < 256) {
            unsigned suf = v;
            for (int q = w8 + 1; q < 8; ++q) suf += wtot[q];
            if ((int)suf >= k && (int)(suf - h0) < k) {
                s_prefix = prefix | ((unsigned)tid << shift);
                s_k = k - (int)(suf - h0);
            }
        }
        __syncthreads();
    }
    if (tid == 0) {
        g_thresh[b] = s_prefix;
        g_ties[b]   = s_k;
    }
}

// ---------------- kernel 2a: grid-parallel flags + block-sorted compaction ----------
__global__ void flags1_kernel(const float* __restrict__ prop) {
    int b = blockIdx.y;
    int tid = threadIdx.x;
    int i = blockIdx.x * 1024 + tid;
    int lane = tid & 31, w = tid >> 5;
    __shared__ int wsum[32];
    __shared__ int blockbase;
    unsigned T = g_thresh[b];
    unsigned u = fkey(prop[(size_t)b * NPIX + i]);
    int gt = (u > T), eq = (u == T);
    g_flags[(size_t)b * NPIX + i] = (unsigned char)gt;   // eq selections patched by flags2
    unsigned ball = __ballot_sync(0xffffffffu, gt);
    int pre = __popc(ball & ((1u << lane) - 1u));
    if (lane == 0) wsum[w] = __popc(ball);
    __syncthreads();
    if (tid == 0) {
        int acc = 0;
        for (int q = 0; q < 32; ++q) { int t = wsum[q]; wsum[q] = acc; acc += t; }
        blockbase = atomicAdd(&g_cnt[b], acc);
    }
    __syncthreads();
    if (gt) g_idx[(size_t)b * KSEL + blockbase + wsum[w] + pre] = i;
    unsigned balle = __ballot_sync(0xffffffffu, eq);
    if (balle) {
        int leader = __ffs(balle) - 1;
        int cnt = __popc(balle);
        int pree = __popc(balle & ((1u << lane) - 1u));
        int basee = 0;
        if (lane == leader) basee = atomicAdd(&g_eqcnt[b], cnt);
        basee = __shfl_sync(0xffffffffu, basee, leader);
        if (eq) g_eqidx[b * 1024 + basee + pree] = i;
    }
}

// ---------------- kernel 2b: tie fixup (n expected ~1) ----------------
__global__ void flags2_kernel() {
    int b = blockIdx.x;
    int n = g_eqcnt[b];
    int ties = g_ties[b];
    for (int e = threadIdx.x; e < n; e += 256) {
        int idx = g_eqidx[b * 1024 + e];
        int rank = 0;
        for (int q = 0; q < n; ++q)
            rank += (g_eqidx[b * 1024 + q] < idx) ? 1 : 0;
        if (rank < ties) {
            g_flags[(size_t)b * NPIX + idx] = 1;
            int pos = atomicAdd(&g_cnt[b], 1);
            g_idx[(size_t)b * KSEL + pos] = idx;
        }
    }
}

// ---------------- kernel 3: fused LN + MLP, half-chunk double-buffered weights ----------
__global__ void __launch_bounds__(NTHR, 3)
main_kernel(const float* __restrict__ x,
            const float* __restrict__ lnscale, const float* __restrict__ lnbias,
            const float* __restrict__ b1g, const float* __restrict__ b2g,
            float* __restrict__ out) {
    int tid = threadIdx.x;
    int b = blockIdx.y;

    // ---- merged pass-through copy path ----
    if (blockIdx.x >= MAINBLK) {
        int t0 = (blockIdx.x - MAINBLK) * COPYTOK + tid;
        const float* xb = x + (size_t)b * CH * NPIX;
        float* ob = out + (size_t)b * CH * NPIX;
        #pragma unroll
        for (int k = 0; k < COPYTOK / NTHR; ++k) {
            int i = t0 + k * NTHR;
            if (g_flags[(size_t)b * NPIX + i]) continue;
            #pragma unroll 8
            for (int c = 0; c < CH; ++c)
                ob[(size_t)c * NPIX + i] = xb[(size_t)c * NPIX + i];
        }
        return;
    }

    extern __shared__ char sm[];
    float* sT  = (float*)(sm + OFF_T);
    unsigned* sB1h = (unsigned*)(sm + OFF_B1);
    float* sB2 = (float*)(sm + OFF_B2);
    float* sLS = (float*)(sm + OFF_LS);
    float* sLB = (float*)(sm + OFF_LB);
    int*   sIdx = (int*)(sm + OFF_IDX);
    unsigned smem_base = (unsigned)__cvta_generic_to_shared(sm);

    int lane = tid & 31, w = tid >> 5;
    int tb = w * 32;
    int n0 = blockIdx.x * TOKB;

    int r = lane >> 2;
    int c2 = (lane & 3) * 2;
    int r15 = lane & 15;
    int colsel = ((lane >> 4) & 1) * 8;
    int row0a = tb + r,      row1a = row0a + 8;
    int row0b = tb + 16 + r, row1b = row0b + 8;

    // ---- stage half-chunk 0 (async, overlaps gathers) ----
    {
        const char* src = (const char*)g_whc;
        unsigned dst = smem_base + OFF_W;
        for (int i = tid * 16; i < HC_BYTES; i += NTHR * 16) cp16(dst + i, src + i);
        asm volatile("cp.async.commit_group;");
    }

    // ---- token index list + params, then gather x tile ----
    sIdx[tid] = g_idx[(size_t)b * KSEL + n0 + tid];
    for (int i = tid; i < HID; i += NTHR)
        sB1h[i] = pack_h2(make_float2(b1g[2 * i], b1g[2 * i + 1]));
    if (tid < 2 * CH) {
        sB2[tid] = b2g[tid];
        sLS[tid] = lnscale[tid];
        sLB[tid] = lnbias[tid];
    }
    __syncthreads();
    const float* xb = x + (size_t)b * CH * NPIX;
    {
        int gi = sIdx[tid];
        #pragma unroll 8
        for (int c = 0; c < CH; ++c)
            sT[tid * ST_S + c] = xb[(size_t)c * NPIX + gi];
    }
    __syncthreads();

    for (int layer = 0; layer < 2; ++layer) {
        // ---- LN stats: 1 lane per token ----
        float mu, rs;
        {
            const float* rowp = sT + (tb + lane) * ST_S;
            float s = 0.f, s2 = 0.f;
            #pragma unroll
            for (int k = 0; k < 64; k += 4) {
                float4 v = *(const float4*)(rowp + k);
                s  += v.x + v.y + v.z + v.w;
                s2 += v.x * v.x + v.y * v.y + v.z * v.z + v.w * v.w;
            }
            mu = s * (1.f / 64.f);
            float var = s2 * (1.f / 64.f) - mu * mu;
            rs = rsqrtf(var + 1e-5f);
        }
        float mu0a = __shfl_sync(0xffffffffu, mu, r);
        float rs0a = __shfl_sync(0xffffffffu, rs, r);
        float mu1a = __shfl_sync(0xffffffffu, mu, r + 8);
        float rs1a = __shfl_sync(0xffffffffu, rs, r + 8);
        float mu0b = __shfl_sync(0xffffffffu, mu, r + 16);
        float rs0b = __shfl_sync(0xffffffffu, rs, r + 16);
        float mu1b = __shfl_sync(0xffffffffu, mu, r + 24);
        float rs1b = __shfl_sync(0xffffffffu, rs, r + 24);

        // ---- build GEMM1 A-fragments (Xn), fp16, two M-tiles ----
        unsigned aXa[16], aXb[16];
        #pragma unroll
        for (int kt = 0; kt < 4; ++kt) {
            int cA = kt * 16 + c2;
            float2 lsA = *(const float2*)(sLS + layer * 64 + cA);
            float2 lbA = *(const float2*)(sLB + layer * 64 + cA);
            float2 lsB = *(const float2*)(sLS + layer * 64 + cA + 8);
            float2 lbB = *(const float2*)(sLB + layer * 64 + cA + 8);
            float2 v;
            v = *(const float2*)(sT + row0a * ST_S + cA);
            v.x = (v.x - mu0a) * rs0a * lsA.x + lbA.x;
            v.y = (v.y - mu0a) * rs0a * lsA.y + lbA.y;
            aXa[kt * 4 + 0] = pack_h2(v);
            v = *(const float2*)(sT + row1a * ST_S + cA);
            v.x = (v.x - mu1a) * rs1a * lsA.x + lbA.x;
            v.y = (v.y - mu1a) * rs1a * lsA.y + lbA.y;
            aXa[kt * 4 + 1] = pack_h2(v);
            v = *(const float2*)(sT + row0a * ST_S + cA + 8);
            v.x = (v.x - mu0a) * rs0a * lsB.x + lbB.x;
            v.y = (v.y - mu0a) * rs0a * lsB.y + lbB.y;
            aXa[kt * 4 + 2] = pack_h2(v);
            v = *(const float2*)(sT + row1a * ST_S + cA + 8);
            v.x = (v.x - mu1a) * rs1a * lsB.x + lbB.x;
            v.y = (v.y - mu1a) * rs1a * lsB.y + lbB.y;
            aXa[kt * 4 + 3] = pack_h2(v);

            v = *(const float2*)(sT + row0b * ST_S + cA);
            v.x = (v.x - mu0b) * rs0b * lsA.x + lbA.x;
            v.y = (v.y - mu0b) * rs0b * lsA.y + lbA.y;
            aXb[kt * 4 + 0] = pack_h2(v);
            v = *(const float2*)(sT + row1b * ST_S + cA);
            v.x = (v.x - mu1b) * rs1b * lsA.x + lbA.x;
            v.y = (v.y - mu1b) * rs1b * lsA.y + lbA.y;
            aXb[kt * 4 + 1] = pack_h2(v);
            v = *(const float2*)(sT + row0b * ST_S + cA + 8);
            v.x = (v.x - mu0b) * rs0b * lsB.x + lbB.x;
            v.y = (v.y - mu0b) * rs0b * lsB.y + lbB.y;
            aXb[kt * 4 + 2] = pack_h2(v);
            v = *(const float2*)(sT + row1b * ST_S + cA + 8);
            v.x = (v.x - mu1b) * rs1b * lsB.x + lbB.x;
            v.y = (v.y - mu1b) * rs1b * lsB.y + lbB.y;
            aXb[kt * 4 + 3] = pack_h2(v);
        }

        float d2a[32], d2b[32];
        #pragma unroll
        for (int i = 0; i < 32; ++i) { d2a[i] = 0.f; d2b[i] = 0.f; }

        for (int q = 0; q < 4; ++q) {
            int hc = layer * 4 + q;
            unsigned wbase = smem_base + OFF_W + (hc & 1) * HC_BYTES;

            __syncthreads();   // all warps done reading buf[(hc+1)&1] (= hc-1's data)
            if (hc + 1 < 8) {
                const char* src = (const char*)(g_whc + (hc + 1) * HC_ELEMS);
                unsigned dst = smem_base + OFF_W + ((hc + 1) & 1) * HC_BYTES;
                for (int i = tid * 16; i < HC_BYTES; i += NTHR * 16) cp16(dst + i, src + i);
                asm volatile("cp.async.commit_group;");
                asm volatile("cp.async.wait_group 1;");
            } else {
                asm volatile("cp.async.wait_group 0;");
            }
            __syncthreads();   // half-chunk hc visible to all warps

            // ---- epilogue-lag pipeline over jg=0..3 ----
            unsigned a2a[4], a2b[4];
            #pragma unroll
            for (int jg = 0; jg < 4; ++jg) {
                float d1a[8], d1b[8];
                #pragma unroll
                for (int i = 0; i < 8; ++i) { d1a[i] = 0.f; d1b[i] = 0.f; }
                #pragma unroll
                for (int kt = 0; kt < 4; ++kt) {
                    unsigned bh[4];
                    unsigned boff = (unsigned)((kt * 16 + r15) * WH_S + jg * 16 + colsel) * 2;
                    ldsm_x4t(bh, wbase + boff);
                    mma_f16(d1a,     aXa + kt * 4, bh[0], bh[1]);
                    mma_f16(d1b,     aXb + kt * 4, bh[0], bh[1]);
                    mma_f16(d1a + 4, aXa + kt * 4, bh[2], bh[3]);
                    mma_f16(d1b + 4, aXb + kt * 4, bh[2], bh[3]);
                }
                if (jg > 0) {
                    int jp = jg - 1;
                    #pragma unroll
                    for (int np = 0; np < 4; ++np) {
                        unsigned bh[4];
                        unsigned boff = W2REG + (unsigned)((jp * 16 + r15) * WH_S + np * 16 + colsel) * 2;
                        ldsm_x4t(bh, wbase + boff);
                        mma_f16(d2a + np * 8,     a2a, bh[0], bh[1]);
                        mma_f16(d2b + np * 8,     a2b, bh[0], bh[1]);
                        mma_f16(d2a + np * 8 + 4, a2a, bh[2], bh[3]);
                        mma_f16(d2b + np * 8 + 4, a2b, bh[2], bh[3]);
                    }
                }
                {
                    int pb = (layer * HID + q * 64 + jg * 16) >> 1;
                    unsigned b0 = sB1h[pb + (c2 >> 1)];
                    unsigned b8 = sB1h[pb + 4 + (c2 >> 1)];
                    __half2 b0h = *(__half2*)&b0, b8h = *(__half2*)&b8;
                    __half2 t; unsigned tu;
                    #define GEPI(dst, dd, bb) \
                        tu = pack_h2(make_float2((dd)[0], (dd)[1])); \
                        t = __hadd2(*(__half2*)&tu, bb); \
                        dst = gelu_h2(*(unsigned*)&t);
                    GEPI(a2a[0], d1a + 0, b0h); GEPI(a2a[1], d1a + 2, b0h);
                    GEPI(a2a[2], d1a + 4, b8h); GEPI(a2a[3], d1a + 6, b8h);
                    GEPI(a2b[0], d1b + 0, b0h); GEPI(a2b[1], d1b + 2, b0h);
                    GEPI(a2b[2], d1b + 4, b8h); GEPI(a2b[3], d1b + 6, b8h);
                    #undef GEPI
                }
            }
            // drain: GEMM2 for jg=3 (buffer hc still valid)
            #pragma unroll
            for (int np = 0; np < 4; ++np) {
                unsigned bh[4];
                unsigned boff = W2REG + (unsigned)((3 * 16 + r15) * WH_S + np * 16 + colsel) * 2;
                ldsm_x4t(bh, wbase + boff);
                mma_f16(d2a + np * 8,     a2a, bh[0], bh[1]);
                mma_f16(d2b + np * 8,     a2b, bh[0], bh[1]);
                mma_f16(d2a + np * 8 + 4, a2a, bh[2], bh[3]);
                mma_f16(d2b + np * 8 + 4, a2b, bh[2], bh[3]);
            }
        }

        // ---- unconditional residual add into sT (warp-local rows) ----
        {
            #pragma unroll
            for (int nt = 0; nt < 8; ++nt) {
                int c0 = nt * 8 + c2;
                float2 bv = *(const float2*)(sB2 + layer * 64 + c0);
                sT[row0a * ST_S + c0]     += d2a[nt * 4 + 0] + bv.x;
                sT[row0a * ST_S + c0 + 1] += d2a[nt * 4 + 1] + bv.y;
                sT[row1a * ST_S + c0]     += d2a[nt * 4 + 2] + bv.x;
                sT[row1a * ST_S + c0 + 1] += d2a[nt * 4 + 3] + bv.y;
                sT[row0b * ST_S + c0]     += d2b[nt * 4 + 0] + bv.x;
                sT[row0b * ST_S + c0 + 1] += d2b[nt * 4 + 1] + bv.y;
                sT[row1b * ST_S + c0]     += d2b[nt * 4 + 2] + bv.x;
                sT[row1b * ST_S + c0 + 1] += d2b[nt * 4 + 3] + bv.y;
            }
        }
        __syncwarp();
    }

    // ---- scatter store ----
    __syncthreads();
    float* ob = out + (size_t)b * CH * NPIX;
    {
        int gi = sIdx[tid];
        #pragma unroll 8
        for (int c = 0; c < CH; ++c)
            ob[(size_t)c * NPIX + gi] = sT[tid * ST_S + c];
    }
}

// ---------------- launch ----------------
extern "C" void kernel_launch(void* const* d_in, const int* in_sizes, int n_in,
                              void* d_out, int out_size) {
    const float* x    = (const float*)d_in[0];
    const float* prop = (const float*)d_in[1];
    const float* lns  = (const float*)d_in[2];
    const float* lnb  = (const float*)d_in[3];
    const float* w1   = (const float*)d_in[4];
    const float* b1   = (const float*)d_in[5];
    const float* w2   = (const float*)d_in[6];
    const float* b2   = (const float*)d_in[7];
    float* out = (float*)d_out;

    cudaFuncSetAttribute(main_kernel, cudaFuncAttributeMaxDynamicSharedMemorySize, SMEM_BYTES);
    int sel_smem = (NPIX + 256 + CAP) * 4;
    cudaFuncSetAttribute(select_kernel, cudaFuncAttributeMaxDynamicSharedMemorySize, sel_smem);

    select_kernel<<<BATCH + 2, 1024, sel_smem>>>(prop, w1, w2);
    dim3 fgrid(NPIX / 1024, BATCH);
    flags1_kernel<<<fgrid, 1024>>>(prop);
    flags2_kernel<<<BATCH, 256>>>();
    dim3 grid(MAINBLK + COPYBLK, BATCH);
    main_kernel<<<grid, NTHR, SMEM_BYTES>>>(x, lns, lnb, b1, b2, out);
}